// round 9
// baseline (speedup 1.0000x reference)
#include <cuda_runtime.h>
#include <cuda_fp16.h>
#include <math.h>

#define F8c   16
#define F2c   64
#define DIM6c 455
#define Gc    4096
#define MROWS 8192     // B*T*F8
#define BTc   512      // B*T
#define XROWS 16384    // B*H*C
#define TROWS 32768    // B*T*F2
#define NBPAD 512
#define DSCALE   256.0f
#define DUNSCALE (1.0f/256.0f)

__device__ __forceinline__ unsigned int smem_u32(const void* p) {
    return (unsigned int)__cvta_generic_to_shared(p);
}
#define CP_ASYNC16(dst, src) \
    asm volatile("cp.async.cg.shared.global [%0], [%1], 16;" :: "r"(dst), "l"(src))
#define CP_COMMIT()  asm volatile("cp.async.commit_group;")
#define CP_WAIT1()   asm volatile("cp.async.wait_group 1;")
#define CP_WAIT0()   asm volatile("cp.async.wait_group 0;")

#define MMA_F16(c0,c1,c2,c3,a0,a1,a2,a3,b0,b1) \
    asm volatile("mma.sync.aligned.m16n8k16.row.col.f32.f16.f16.f32 " \
        "{%0,%1,%2,%3}, {%4,%5,%6,%7}, {%8,%9}, {%0,%1,%2,%3};" \
        : "+f"(c0), "+f"(c1), "+f"(c2), "+f"(c3) \
        : "r"(a0), "r"(a1), "r"(a2), "r"(a3), "r"(b0), "r"(b1))

#define LDSM4(r0,r1,r2,r3,addr) \
    asm volatile("ldmatrix.sync.aligned.m8n8.x4.shared.b16 {%0,%1,%2,%3}, [%4];" \
        : "=r"(r0), "=r"(r1), "=r"(r2), "=r"(r3) : "r"(addr))

// -------- scratch --------
__device__ float   g_H  [MROWS * 10];
__device__ __half  g_sigH[(size_t)MROWS * Gc];   // fp16 sig, [m][k]
__device__ __half  g_BnH [(size_t)NBPAD * Gc];   // fp16 Dout^T * 256, [n][k]
__device__ __half  g_Ah [8192 * 455];            // per-l A_l [(bt*d+m)][(f*d+u)]
__device__ __half  g_Bh [1024 * 455];            // per-l B_l [(g2*d+v)][(f*d+u)]
__device__ __half  g_TJh[BTc * F2c * DIM6c];

#define AB0 0
#define AB1 (8192*1)
#define AB2 (8192*10)
#define AB3 (8192*35)
#define AB4 (8192*84)
#define AB5 (8192*165)
#define AB6 (8192*286)
#define BB0 0
#define BB1 (1024*1)
#define BB2 (1024*10)
#define BB3 (1024*35)
#define BB4 (1024*84)
#define BB5 (1024*165)
#define BB6 (1024*286)

// ================= kernel H =================
__global__ void kH(const float* __restrict__ traj,
                   const float* __restrict__ w1s,
                   const float* __restrict__ w1v) {
    int row = blockIdx.x * blockDim.x + threadIdx.x;
    if (row >= MROWS) return;
    int bt = row >> 4, c = row & 15;
    const float* tr = traj + bt * 10;
    float tv[9];
    #pragma unroll
    for (int q = 0; q < 9; q++) tv[q] = tr[q];
    float s = tr[9];
    float* out = g_H + row * 10;
    out[0] = s * w1s[c];
    const float inv3 = 0.57735026918962576f;
    #pragma unroll
    for (int v = 0; v < 3; v++) {
        #pragma unroll
        for (int m = 0; m < 3; m++) {
            float a = 0.f;
            #pragma unroll
            for (int u = 0; u < 3; u++)
                a += tv[u*3 + m] * w1v[c*9 + u*3 + v];
            out[1 + v*3 + m] = a * inv3;
        }
    }
}

// ============ kSig: g_sigH[m][k] = fp16(relu(H[m].Din[k])) ============
__global__ __launch_bounds__(256) void kSig(const float* __restrict__ Din) {
    __shared__ float Hs[32][10];
    const int m0 = blockIdx.y * 32;
    const int k  = blockIdx.x * 256 + threadIdx.x;
    for (int i = threadIdx.x; i < 320; i += 256)
        Hs[i/10][i%10] = g_H[m0*10 + i];
    __syncthreads();
    float dr[10];
    #pragma unroll
    for (int q = 0; q < 10; q++) dr[q] = Din[k*10 + q];
    #pragma unroll 4
    for (int m = 0; m < 32; m++) {
        float a = 0.f;
        #pragma unroll
        for (int q = 0; q < 10; q++) a += Hs[m][q] * dr[q];
        g_sigH[(size_t)(m0 + m) * Gc + k] = __float2half_rn(fmaxf(a, 0.f));
    }
}

// ============ kCvtT: g_BnH[n][k] = fp16(Dout[k][n] * 256) ============
__global__ __launch_bounds__(256) void kCvtT(const float* __restrict__ Dout) {
    __shared__ unsigned short t[32][33];
    const int k0 = blockIdx.x * 32;
    const int n0 = blockIdx.y * 32;
    const int tx = threadIdx.x & 31, ty = threadIdx.x >> 5;
    #pragma unroll
    for (int j = 0; j < 4; j++) {
        int k = k0 + ty + j*8, n = n0 + tx;
        float v = (n < DIM6c) ? Dout[(size_t)k * DIM6c + n] * DSCALE : 0.f;
        t[ty + j*8][tx] = __half_as_ushort(__float2half_rn(v));
    }
    __syncthreads();
    #pragma unroll
    for (int j = 0; j < 4; j++) {
        int n = n0 + ty + j*8, k = k0 + tx;
        g_BnH[(size_t)n * Gc + k] = __ushort_as_half(t[tx][ty + j*8]);
    }
}

// ===== scatter one C element into per-l fp16 A (M-major: [btm][fu]) =====
__device__ __forceinline__ void scatterA(int row, int col, float val) {
    if (col >= DIM6c) return;
    __half tv = __float2half_rn(val);
    int bt = row >> 4, f = row & 15;
    if (col < 1) {
        g_Ah[AB0 + bt * 16 + f] = tv;
    } else if (col < 10) {
        int r = col - 1, u = r / 3, m = r - u*3;
        g_Ah[AB1 + (bt*3 + m) * 48 + f*3 + u] = tv;
    } else if (col < 35) {
        int r = col - 10, u = r / 5, m = r - u*5;
        g_Ah[AB2 + (bt*5 + m) * 80 + f*5 + u] = tv;
    } else if (col < 84) {
        int r = col - 35, u = r / 7, m = r - u*7;
        g_Ah[AB3 + (bt*7 + m) * 112 + f*7 + u] = tv;
    } else if (col < 165) {
        int r = col - 84, u = r / 9, m = r - u*9;
        g_Ah[AB4 + (bt*9 + m) * 144 + f*9 + u] = tv;
    } else if (col < 286) {
        int r = col - 165, u = r / 11, m = r - u*11;
        g_Ah[AB5 + (bt*11 + m) * 176 + f*11 + u] = tv;
    } else {
        int r = col - 286, u = r / 13, m = r - u*13;
        g_Ah[AB6 + (bt*13 + m) * 208 + f*13 + u] = tv;
    }
}

// ============ kBh: fp16 mma GEMM with ldmatrix. CTA 128x128, BK=64 ====
#define STAGE_B 18432              // 128*72*2 bytes
__global__ __launch_bounds__(256) void kBh() {
    extern __shared__ __align__(16) char smb[];
    const int n0 = blockIdx.x * 128;
    const int m0 = blockIdx.y * 128;
    const int tid = threadIdx.x;
    const int wid = tid >> 5, lane = tid & 31;
    const int wm = wid >> 1, wn = wid & 1;
    const int lr = lane >> 2;
    const int lc = lane & 3;

    float acc[2][8][4];
    #pragma unroll
    for (int mi = 0; mi < 2; mi++)
        #pragma unroll
        for (int nj = 0; nj < 8; nj++)
            #pragma unroll
            for (int r = 0; r < 4; r++) acc[mi][nj][r] = 0.f;

    auto issue = [&](int buf, int k0) {
        #pragma unroll
        for (int i = 0; i < 4; i++) {
            int id = tid + i*256;
            int row = id >> 3, cc = id & 7;
            CP_ASYNC16(smem_u32(smb + buf*STAGE_B + row*144 + cc*16),
                       g_sigH + (size_t)(m0 + row) * Gc + k0 + cc*8);
            CP_ASYNC16(smem_u32(smb + 2*STAGE_B + buf*STAGE_B + row*144 + cc*16),
                       g_BnH + (size_t)(n0 + row) * Gc + k0 + cc*8);
        }
    };

    issue(0, 0);  CP_COMMIT();
    issue(1, 64); CP_COMMIT();

    // ldmatrix lane addressing components
    const int a_row_in = (lane & 15);            // row within 16-row frag
    const int a_koff   = (lane >> 4) << 4;       // 0 or 16 bytes
    const int b_row_in = ((lane >> 4) << 3) + (lane & 7);
    const int b_koff   = ((lane >> 3) & 1) << 4;

    const int NIT = Gc / 64;
    for (int it = 0; it < NIT; it++) {
        const int buf = it & 1;
        const unsigned int Abase = smem_u32(smb + buf*STAGE_B);
        const unsigned int Bbase = smem_u32(smb + 2*STAGE_B + buf*STAGE_B);
        CP_WAIT1();
        __syncthreads();

        #pragma unroll
        for (int kc = 0; kc < 4; kc++) {
            unsigned int afr[2][4];
            #pragma unroll
            for (int mi = 0; mi < 2; mi++) {
                int row = wm*32 + mi*16 + a_row_in;
                LDSM4(afr[mi][0], afr[mi][1], afr[mi][2], afr[mi][3],
                      Abase + row*144 + kc*32 + a_koff);
            }
            unsigned int bfr[8][2];
            #pragma unroll
            for (int njp = 0; njp < 4; njp++) {
                int row = wn*64 + njp*16 + b_row_in;
                LDSM4(bfr[2*njp][0], bfr[2*njp][1], bfr[2*njp+1][0], bfr[2*njp+1][1],
                      Bbase + row*144 + kc*32 + b_koff);
            }
            #pragma unroll
            for (int nj = 0; nj < 8; nj++)
                #pragma unroll
                for (int mi = 0; mi < 2; mi++)
                    MMA_F16(acc[mi][nj][0], acc[mi][nj][1], acc[mi][nj][2], acc[mi][nj][3],
                            afr[mi][0], afr[mi][1], afr[mi][2], afr[mi][3],
                            bfr[nj][0], bfr[nj][1]);
        }
        __syncthreads();
        int nk = (it + 2) * 64;
        if (nk < Gc) issue(buf, nk);
        CP_COMMIT();
    }

    #pragma unroll
    for (int mi = 0; mi < 2; mi++) {
        #pragma unroll
        for (int nj = 0; nj < 8; nj++) {
            int row = m0 + wm*32 + mi*16 + lr;
            int col = n0 + wn*64 + nj*8 + lc*2;
            scatterA(row,     col,     acc[mi][nj][0] * DUNSCALE);
            scatterA(row,     col + 1, acc[mi][nj][1] * DUNSCALE);
            scatterA(row + 8, col,     acc[mi][nj][2] * DUNSCALE);
            scatterA(row + 8, col + 1, acc[mi][nj][3] * DUNSCALE);
        }
    }
}

// ============ kWt: g_Bh[l][(g2*d+v)][(f*d+u)] = fp16(w2[f][g2][u][v]) ===
template<int L, int BBASE>
__device__ __forceinline__ void kWt_body(const float* __restrict__ wl) {
    constexpr int d = 2*L + 1;
    constexpr int K = 16 * d;
    int idx = blockIdx.x * 256 + threadIdx.x;
    if (idx >= 64 * d * K) return;
    int n = idx / K, k = idx - n * K;
    int g2 = n / d, v = n - g2 * d;
    int f = k / d, u = k - f * d;
    g_Bh[BBASE + idx] = __float2half_rn(wl[((f*64 + g2) * d + u) * d + v]);
}
__global__ __launch_bounds__(256) void kWt(
    const float* w0, const float* w1, const float* w2p, const float* w3,
    const float* w4, const float* w5, const float* w6) {
    switch (blockIdx.y) {
        case 0: kWt_body<0,BB0>(w0);  break;
        case 1: kWt_body<1,BB1>(w1);  break;
        case 2: kWt_body<2,BB2>(w2p); break;
        case 3: kWt_body<3,BB3>(w3);  break;
        case 4: kWt_body<4,BB4>(w4);  break;
        case 5: kWt_body<5,BB5>(w5);  break;
        case 6: kWt_body<6,BB6>(w6);  break;
    }
}

// ============ kCgemm: per-l C = A_l @ B_l^T (fp16 mma), write g_TJh ======
// BM=128 (btm), BN=64 (g2v), k16 steps; A/B smem row stride 24 halves
template<int L, int OFF, int ABASE, int BBASE>
__device__ __forceinline__ void kCmma_body(__half* Ash, __half* Bsh) {
    constexpr int d    = 2*L + 1;
    constexpr int Mdim = 512 * d;
    constexpr int Ndim = 64 * d;
    constexpr int K    = 16 * d;
    constexpr int TM   = Mdim / 128;
    constexpr int TN   = Ndim / 64;
    const int tile = blockIdx.x;
    if (tile >= TM * TN) return;
    const int m0 = (tile % TM) * 128;
    const int n0 = (tile / TM) * 64;
    const int tid = threadIdx.x;
    const int wid = tid >> 5, lane = tid & 31;
    const int wm = wid >> 1, wn = wid & 1;
    const int lr = lane >> 2, lc = lane & 3;
    const unsigned int* A32 = (const unsigned int*)Ash;
    const unsigned int* B32 = (const unsigned int*)Bsh;

    float acc[2][4][4];
    #pragma unroll
    for (int mi = 0; mi < 2; mi++)
        #pragma unroll
        for (int nj = 0; nj < 4; nj++)
            #pragma unroll
            for (int r = 0; r < 4; r++) acc[mi][nj][r] = 0.f;

    for (int k0 = 0; k0 < K; k0 += 16) {
        {
            int row = tid >> 1, ch = tid & 1;
            CP_ASYNC16(smem_u32(Ash + row*24 + ch*8),
                       g_Ah + ABASE + (size_t)(m0 + row) * K + k0 + ch*8);
            if (tid < 128) {
                int rb = tid >> 1, cb = tid & 1;
                CP_ASYNC16(smem_u32(Bsh + rb*24 + cb*8),
                           g_Bh + BBASE + (size_t)(n0 + rb) * K + k0 + cb*8);
            }
        }
        CP_COMMIT();
        CP_WAIT0();
        __syncthreads();

        unsigned int afr[2][4];
        #pragma unroll
        for (int mi = 0; mi < 2; mi++) {
            int rb = wm*32 + mi*16 + lr;
            afr[mi][0] = A32[(rb    )*12 + lc    ];
            afr[mi][1] = A32[(rb + 8)*12 + lc    ];
            afr[mi][2] = A32[(rb    )*12 + lc + 4];
            afr[mi][3] = A32[(rb + 8)*12 + lc + 4];
        }
        #pragma unroll
        for (int nj = 0; nj < 4; nj++) {
            int nb = wn*32 + nj*8 + lr;
            unsigned int b0 = B32[nb*12 + lc    ];
            unsigned int b1 = B32[nb*12 + lc + 4];
            #pragma unroll
            for (int mi = 0; mi < 2; mi++)
                MMA_F16(acc[mi][nj][0], acc[mi][nj][1], acc[mi][nj][2], acc[mi][nj][3],
                        afr[mi][0], afr[mi][1], afr[mi][2], afr[mi][3], b0, b1);
        }
        __syncthreads();
    }

    const float scale = 0.25f * rsqrtf((float)d);
    #pragma unroll
    for (int mi = 0; mi < 2; mi++) {
        #pragma unroll
        for (int nj = 0; nj < 4; nj++) {
            #pragma unroll
            for (int rr = 0; rr < 2; rr++) {
                int row = m0 + wm*32 + mi*16 + lr + rr*8;
                int bt = row / d, mm = row - bt * d;
                #pragma unroll
                for (int cc = 0; cc < 2; cc++) {
                    int col = n0 + wn*32 + nj*8 + lc*2 + cc;
                    int g2 = col / d, v = col - g2 * d;
                    g_TJh[(size_t)(bt*64 + g2) * DIM6c + OFF + v*d + mm] =
                        __float2half_rn(acc[mi][nj][rr*2 + cc] * scale);
                }
            }
        }
    }
}
__global__ __launch_bounds__(256) void kCgemm() {
    __shared__ __align__(16) __half Ash[128 * 24];
    __shared__ __align__(16) __half Bsh[64 * 24];
    switch (blockIdx.y) {
        case 0: kCmma_body<0,0,  AB0,BB0>(Ash,Bsh); break;
        case 1: kCmma_body<1,1,  AB1,BB1>(Ash,Bsh); break;
        case 2: kCmma_body<2,10, AB2,BB2>(Ash,Bsh); break;
        case 3: kCmma_body<3,35, AB3,BB3>(Ash,Bsh); break;
        case 4: kCmma_body<4,84, AB4,BB4>(Ash,Bsh); break;
        case 5: kCmma_body<5,165,AB5,BB5>(Ash,Bsh); break;
        case 6: kCmma_body<6,286,AB6,BB6>(Ash,Bsh); break;
    }
}

// ============ kDmma: out[r][i] = sum_j A[r][j] * ico[i][j], fp16 mma ========
__global__ __launch_bounds__(256) void kDmma(const float* __restrict__ x,
                                             const float* __restrict__ ico,
                                             float* __restrict__ out, int I) {
    __shared__ __half As[128][36];
    __shared__ __half Bs[64][36];
    const int r0 = blockIdx.x * 128;
    const bool fromX = (r0 < XROWS);
    const int tid = threadIdx.x;
    const int wid = tid >> 5, lane = tid & 31;
    const int wm = wid >> 1, wn = wid & 1;
    const int lr = lane >> 2;
    const int lc = lane & 3;
    const unsigned int* A32 = (const unsigned int*)&As[0][0];
    const unsigned int* B32 = (const unsigned int*)&Bs[0][0];

    float acc[2][4][4];
    #pragma unroll
    for (int mi = 0; mi < 2; mi++)
        #pragma unroll
        for (int nj = 0; nj < 4; nj++)
            #pragma unroll
            for (int r = 0; r < 4; r++) acc[mi][nj][r] = 0.f;

    for (int j0 = 0; j0 < 480; j0 += 32) {
        #pragma unroll
        for (int i = 0; i < 16; i++) {
            int idx = i*256 + tid;
            int r = idx >> 5, kk = idx & 31;
            int j = j0 + kk;
            __half v = __float2half_rn(0.f);
            if (j < DIM6c) {
                if (fromX) v = __float2half_rn(x[(size_t)(r0 + r) * DIM6c + j]);
                else       v = g_TJh[(size_t)(r0 - XROWS + r) * DIM6c + j];
            }
            As[r][kk] = v;
        }
        #pragma unroll
        for (int i = 0; i < 8; i++) {
            int idx = i*256 + tid;
            int n = idx >> 5, kk = idx & 31;
            int j = j0 + kk;
            Bs[n][kk] = (n < I && j < DIM6c) ?
                __float2half_rn(ico[(size_t)n * DIM6c + j]) : __float2half_rn(0.f);
        }
        __syncthreads();

        #pragma unroll
        for (int kc = 0; kc < 2; kc++) {
            const int w0 = kc*8 + lc;
            unsigned int afr[2][4];
            #pragma unroll
            for (int mi = 0; mi < 2; mi++) {
                int rb = wm*32 + mi*16 + lr;
                afr[mi][0] = A32[(rb    )*18 + w0    ];
                afr[mi][1] = A32[(rb + 8)*18 + w0    ];
                afr[mi][2] = A32[(rb    )*18 + w0 + 4];
                afr[mi][3] = A32[(rb + 8)*18 + w0 + 4];
            }
            #pragma unroll
            for (int nj = 0; nj < 4; nj++) {
                int nb = wn*32 + nj*8 + lr;
                unsigned int b0 = B32[nb*18 + w0    ];
                unsigned int b1 = B32[nb*18 + w0 + 4];
                #pragma unroll
                for (int mi = 0; mi < 2; mi++)
                    MMA_F16(acc[mi][nj][0], acc[mi][nj][1], acc[mi][nj][2], acc[mi][nj][3],
                            afr[mi][0], afr[mi][1], afr[mi][2], afr[mi][3], b0, b1);
            }
        }
        __syncthreads();
    }

    #pragma unroll
    for (int mi = 0; mi < 2; mi++) {
        #pragma unroll
        for (int nj = 0; nj < 4; nj++) {
            int row = r0 + wm*32 + mi*16 + lr;
            int col = wn*32 + nj*8 + lc*2;
            if (col < I) {
                out[(size_t)row * I + col] = acc[mi][nj][0];
                out[(size_t)(row + 8) * I + col] = acc[mi][nj][2];
                if (col + 1 < I) {
                    out[(size_t)row * I + col + 1] = acc[mi][nj][1];
                    out[(size_t)(row + 8) * I + col + 1] = acc[mi][nj][3];
                }
            }
        }
    }
}

extern "C" void kernel_launch(void* const* d_in, const int* in_sizes, int n_in,
                              void* d_out, int out_size) {
    const float *x = nullptr, *traj = nullptr, *w1s = nullptr, *w1v = nullptr;
    const float *Din = nullptr, *Dout = nullptr, *ico = nullptr;
    const float* w2[7] = {};
    int icoN = 60;

    for (int i = 0; i < n_in; i++) {
        int sz = in_sizes[i];
        const float* p = (const float*)d_in[i];
        switch (sz) {
            case 7454720: x    = p; break;
            case 5120:    traj = p; break;
            case 16:      w1s  = p; break;
            case 144:     w1v  = p; break;
            case 40960:   Din  = p; break;
            case 1863680: Dout = p; break;
            case 1024:    w2[0] = p; break;
            case 9216:    w2[1] = p; break;
            case 25600:   w2[2] = p; break;
            case 50176:   w2[3] = p; break;
            case 82944:   w2[4] = p; break;
            case 123904:  w2[5] = p; break;
            case 173056:  w2[6] = p; break;
            default:      ico = p; icoN = sz / DIM6c; break;
        }
    }
    float* out = (float*)d_out;

    const int SMEMB = 4 * STAGE_B;   // 73728 bytes
    cudaFuncSetAttribute(kBh, cudaFuncAttributeMaxDynamicSharedMemorySize, SMEMB);

    kH<<<MROWS/256, 256>>>(traj, w1s, w1v);
    kCvtT<<<dim3(Gc/32, NBPAD/32), 256>>>(Dout);
    kSig<<<dim3(Gc/256, MROWS/32), 256>>>(Din);
    kWt<<<dim3(676, 7), 256>>>(w2[0], w2[1], w2[2], w2[3], w2[4], w2[5], w2[6]);

    kBh<<<dim3(4, MROWS/128), 256, SMEMB>>>();

    kCgemm<<<dim3(676, 7), 256>>>();

    kDmma<<<(XROWS + TROWS)/128, 256>>>(x, ico, out, icoN);
}

// round 10
// speedup vs baseline: 1.2468x; 1.2468x over previous
#include <cuda_runtime.h>
#include <cuda_fp16.h>
#include <math.h>

#define F8c   16
#define F2c   64
#define DIM6c 455
#define Gc    4096
#define MROWS 8192     // B*T*F8
#define BTc   512      // B*T
#define XROWS 16384    // B*H*C
#define TROWS 32768    // B*T*F2
#define NBPAD 512
#define DSCALE   256.0f
#define DUNSCALE (1.0f/256.0f)

__device__ __forceinline__ unsigned int f2tf32(float f) {
    unsigned int r;
    asm("cvt.rna.tf32.f32 %0, %1;" : "=r"(r) : "f"(f));
    return r;
}
__device__ __forceinline__ unsigned int smem_u32(const void* p) {
    return (unsigned int)__cvta_generic_to_shared(p);
}
#define CP_ASYNC16(dst, src) \
    asm volatile("cp.async.cg.shared.global [%0], [%1], 16;" :: "r"(dst), "l"(src))
#define CP_COMMIT()  asm volatile("cp.async.commit_group;")
#define CP_WAIT1()   asm volatile("cp.async.wait_group 1;")

#define MMA_TF32(c0,c1,c2,c3,a0,a1,a2,a3,b0,b1) \
    asm volatile("mma.sync.aligned.m16n8k8.row.col.f32.tf32.tf32.f32 " \
        "{%0,%1,%2,%3}, {%4,%5,%6,%7}, {%8,%9}, {%0,%1,%2,%3};" \
        : "+f"(c0), "+f"(c1), "+f"(c2), "+f"(c3) \
        : "r"(a0), "r"(a1), "r"(a2), "r"(a3), "r"(b0), "r"(b1))

#define MMA_F16(c0,c1,c2,c3,a0,a1,a2,a3,b0,b1) \
    asm volatile("mma.sync.aligned.m16n8k16.row.col.f32.f16.f16.f32 " \
        "{%0,%1,%2,%3}, {%4,%5,%6,%7}, {%8,%9}, {%0,%1,%2,%3};" \
        : "+f"(c0), "+f"(c1), "+f"(c2), "+f"(c3) \
        : "r"(a0), "r"(a1), "r"(a2), "r"(a3), "r"(b0), "r"(b1))

// -------- scratch --------
__device__ float          g_H  [MROWS * 10];
__device__ __half         g_sigH[(size_t)MROWS * Gc];   // fp16 sig, [m][k]
__device__ __half         g_BnH [(size_t)NBPAD * Gc];   // fp16 Dout^T * 256, [n][k]
__device__ unsigned int   g_A [8192 * 455];             // per-l A_l tf32
__device__ unsigned int   g_B [1024 * 455];             // per-l B_l tf32
__device__ float          g_TJ[BTc * F2c * DIM6c];

#define AB0 0
#define AB1 (8192*1)
#define AB2 (8192*10)
#define AB3 (8192*35)
#define AB4 (8192*84)
#define AB5 (8192*165)
#define AB6 (8192*286)
#define BB0 0
#define BB1 (1024*1)
#define BB2 (1024*10)
#define BB3 (1024*35)
#define BB4 (1024*84)
#define BB5 (1024*165)
#define BB6 (1024*286)

// ================= kernel H =================
__global__ void kH(const float* __restrict__ traj,
                   const float* __restrict__ w1s,
                   const float* __restrict__ w1v) {
    int row = blockIdx.x * blockDim.x + threadIdx.x;
    if (row >= MROWS) return;
    int bt = row >> 4, c = row & 15;
    const float* tr = traj + bt * 10;
    float tv[9];
    #pragma unroll
    for (int q = 0; q < 9; q++) tv[q] = tr[q];
    float s = tr[9];
    float* out = g_H + row * 10;
    out[0] = s * w1s[c];
    const float inv3 = 0.57735026918962576f;
    #pragma unroll
    for (int v = 0; v < 3; v++) {
        #pragma unroll
        for (int m = 0; m < 3; m++) {
            float a = 0.f;
            #pragma unroll
            for (int u = 0; u < 3; u++)
                a += tv[u*3 + m] * w1v[c*9 + u*3 + v];
            out[1 + v*3 + m] = a * inv3;
        }
    }
}

// ============ kSig: g_sigH[m][k] = fp16(relu(H[m].Din[k])) ============
__global__ __launch_bounds__(256) void kSig(const float* __restrict__ Din) {
    __shared__ float Hs[32][10];
    const int m0 = blockIdx.y * 32;
    const int k  = blockIdx.x * 256 + threadIdx.x;
    for (int i = threadIdx.x; i < 320; i += 256)
        Hs[i/10][i%10] = g_H[m0*10 + i];
    __syncthreads();
    float dr[10];
    #pragma unroll
    for (int q = 0; q < 10; q++) dr[q] = Din[k*10 + q];
    #pragma unroll 4
    for (int m = 0; m < 32; m++) {
        float a = 0.f;
        #pragma unroll
        for (int q = 0; q < 10; q++) a += Hs[m][q] * dr[q];
        g_sigH[(size_t)(m0 + m) * Gc + k] = __float2half_rn(fmaxf(a, 0.f));
    }
}

// ============ kCvtT: g_BnH[n][k] = fp16(Dout[k][n] * 256) ============
__global__ __launch_bounds__(256) void kCvtT(const float* __restrict__ Dout) {
    __shared__ unsigned short t[32][33];
    const int k0 = blockIdx.x * 32;
    const int n0 = blockIdx.y * 32;
    const int tx = threadIdx.x & 31, ty = threadIdx.x >> 5;   // 32 x 8
    #pragma unroll
    for (int j = 0; j < 4; j++) {
        int k = k0 + ty + j*8, n = n0 + tx;
        float v = (n < DIM6c) ? Dout[(size_t)k * DIM6c + n] * DSCALE : 0.f;
        t[ty + j*8][tx] = __half_as_ushort(__float2half_rn(v));
    }
    __syncthreads();
    #pragma unroll
    for (int j = 0; j < 4; j++) {
        int n = n0 + ty + j*8, k = k0 + tx;
        g_BnH[(size_t)n * Gc + k] = __ushort_as_half(t[tx][ty + j*8]);
    }
}

// ===== scatter one C element straight into per-l tf32 A =====
__device__ __forceinline__ void scatterA(int row, int col, float val) {
    if (col >= DIM6c) return;
    unsigned int tv = f2tf32(val);
    int bt = row >> 4, f = row & 15;
    if (col < 1) {
        g_A[AB0 + f * 512 + bt] = tv;
    } else if (col < 10) {
        int r = col - 1, u = r / 3, m = r - u*3;
        g_A[AB1 + (f*3 + u) * (512*3) + bt*3 + m] = tv;
    } else if (col < 35) {
        int r = col - 10, u = r / 5, m = r - u*5;
        g_A[AB2 + (f*5 + u) * (512*5) + bt*5 + m] = tv;
    } else if (col < 84) {
        int r = col - 35, u = r / 7, m = r - u*7;
        g_A[AB3 + (f*7 + u) * (512*7) + bt*7 + m] = tv;
    } else if (col < 165) {
        int r = col - 84, u = r / 9, m = r - u*9;
        g_A[AB4 + (f*9 + u) * (512*9) + bt*9 + m] = tv;
    } else if (col < 286) {
        int r = col - 165, u = r / 11, m = r - u*11;
        g_A[AB5 + (f*11 + u) * (512*11) + bt*11 + m] = tv;
    } else {
        int r = col - 286, u = r / 13, m = r - u*13;
        g_A[AB6 + (f*13 + u) * (512*13) + bt*13 + m] = tv;
    }
}

// ============ kBh: fp16 mma GEMM. CTA 128x128, BK=64, 2-stage cp.async ====
// smem halves, row stride 72 halves (144B): word stride 36 == 4 mod 32 -> no conflicts
#define HSTR 72
#define STAGE_B 18432              // 128*72*2 bytes
__global__ __launch_bounds__(256) void kBh() {
    extern __shared__ __align__(16) char smb[];
    // A0@0, A1@STAGE_B, B0@2*STAGE_B, B1@3*STAGE_B
    const int n0 = blockIdx.x * 128;
    const int m0 = blockIdx.y * 128;
    const int tid = threadIdx.x;
    const int wid = tid >> 5, lane = tid & 31;
    const int wm = wid >> 1, wn = wid & 1;
    const int lr = lane >> 2;
    const int lc = lane & 3;

    float acc[2][8][4];
    #pragma unroll
    for (int mi = 0; mi < 2; mi++)
        #pragma unroll
        for (int nj = 0; nj < 8; nj++)
            #pragma unroll
            for (int r = 0; r < 4; r++) acc[mi][nj][r] = 0.f;

    auto issue = [&](int buf, int k0) {
        #pragma unroll
        for (int i = 0; i < 4; i++) {
            int id = tid + i*256;              // 0..1023
            int row = id >> 3, cc = id & 7;    // 8 x 16B chunks per 128B row
            CP_ASYNC16(smem_u32(smb + buf*STAGE_B + row*144 + cc*16),
                       g_sigH + (size_t)(m0 + row) * Gc + k0 + cc*8);
            CP_ASYNC16(smem_u32(smb + 2*STAGE_B + buf*STAGE_B + row*144 + cc*16),
                       g_BnH + (size_t)(n0 + row) * Gc + k0 + cc*8);
        }
    };

    issue(0, 0);  CP_COMMIT();
    issue(1, 64); CP_COMMIT();

    const int rb0 = wm*32 + lr;
    const int NIT = Gc / 64;   // 64
    for (int it = 0; it < NIT; it++) {
        const int buf = it & 1;
        const unsigned int* A32 = (const unsigned int*)(smb + buf*STAGE_B);
        const unsigned int* B32 = (const unsigned int*)(smb + 2*STAGE_B + buf*STAGE_B);
        CP_WAIT1();
        __syncthreads();

        #pragma unroll
        for (int kc = 0; kc < 4; kc++) {
            const int w0 = kc*8 + lc;          // word offset in 36-word row
            unsigned int afr[2][4];
            #pragma unroll
            for (int mi = 0; mi < 2; mi++) {
                int rb = rb0 + mi*16;
                afr[mi][0] = A32[(rb    )*36 + w0    ];
                afr[mi][1] = A32[(rb + 8)*36 + w0    ];
                afr[mi][2] = A32[(rb    )*36 + w0 + 4];
                afr[mi][3] = A32[(rb + 8)*36 + w0 + 4];
            }
            #pragma unroll
            for (int nj = 0; nj < 8; nj++) {
                int nb = wn*64 + nj*8 + lr;
                unsigned int b0 = B32[nb*36 + w0    ];
                unsigned int b1 = B32[nb*36 + w0 + 4];
                #pragma unroll
                for (int mi = 0; mi < 2; mi++)
                    MMA_F16(acc[mi][nj][0], acc[mi][nj][1], acc[mi][nj][2], acc[mi][nj][3],
                            afr[mi][0], afr[mi][1], afr[mi][2], afr[mi][3], b0, b1);
            }
        }
        __syncthreads();
        int nk = (it + 2) * 64;
        if (nk < Gc) issue(buf, nk);
        CP_COMMIT();
    }

    // epilogue: unscale and scatter into per-l tf32 A layout
    #pragma unroll
    for (int mi = 0; mi < 2; mi++) {
        #pragma unroll
        for (int nj = 0; nj < 8; nj++) {
            int row = m0 + wm*32 + mi*16 + lr;
            int col = n0 + wn*64 + nj*8 + lc*2;
            scatterA(row,     col,     acc[mi][nj][0] * DUNSCALE);
            scatterA(row,     col + 1, acc[mi][nj][1] * DUNSCALE);
            scatterA(row + 8, col,     acc[mi][nj][2] * DUNSCALE);
            scatterA(row + 8, col + 1, acc[mi][nj][3] * DUNSCALE);
        }
    }
}

// ============ kWt: g_B[l][(f*d+u)][(g2*d+v)] = tf32(w2[f][g2][u][v]) ===
template<int L, int BBASE>
__device__ __forceinline__ void kWt_body(const float* __restrict__ wl) {
    constexpr int d = 2*L + 1;
    constexpr int Ndim = 64 * d;
    int idx = blockIdx.x * 256 + threadIdx.x;
    if (idx >= 16 * d * Ndim) return;
    int k = idx / Ndim, n = idx - k * Ndim;
    int f = k / d, u = k - f * d;
    int g2 = n / d, v = n - g2 * d;
    g_B[BBASE + idx] = f2tf32(wl[((f*64 + g2) * d + u) * d + v]);
}
__global__ __launch_bounds__(256) void kWt(
    const float* w0, const float* w1, const float* w2p, const float* w3,
    const float* w4, const float* w5, const float* w6) {
    switch (blockIdx.y) {
        case 0: kWt_body<0,BB0>(w0);  break;
        case 1: kWt_body<1,BB1>(w1);  break;
        case 2: kWt_body<2,BB2>(w2p); break;
        case 3: kWt_body<3,BB3>(w3);  break;
        case 4: kWt_body<4,BB4>(w4);  break;
        case 5: kWt_body<5,BB5>(w5);  break;
        case 6: kWt_body<6,BB6>(w6);  break;
    }
}

// ============ kCgemm: per-l C = A_l @ B_l (tf32 mma.sync), scatter to g_TJ ===
template<int L, int OFF, int ABASE, int BBASE>
__device__ __forceinline__ void kCmma_body(unsigned int (*As)[136],
                                           unsigned int (*Bs)[72]) {
    constexpr int d    = 2*L + 1;
    constexpr int Mdim = 512 * d;
    constexpr int Ndim = 64 * d;
    constexpr int K    = 16 * d;
    constexpr int TM   = Mdim / 128;
    constexpr int TN   = Ndim / 64;
    const int tile = blockIdx.x;
    if (tile >= TM * TN) return;
    const int m0 = (tile % TM) * 128;
    const int n0 = (tile / TM) * 64;
    const int tid = threadIdx.x;
    const int wid = tid >> 5, lane = tid & 31;
    const int wm = wid >> 1, wn = wid & 1;
    const int lr = lane >> 2, lc = lane & 3;

    float acc[2][4][4];
    #pragma unroll
    for (int mi = 0; mi < 2; mi++)
        #pragma unroll
        for (int nj = 0; nj < 4; nj++)
            #pragma unroll
            for (int r = 0; r < 4; r++) acc[mi][nj][r] = 0.f;

    for (int k0 = 0; k0 < K; k0 += 16) {
        #pragma unroll
        for (int i = 0; i < 2; i++) {
            int idx = tid + i*256;
            int k = idx >> 5, c4 = (idx & 31) * 4;
            *(uint4*)&As[k][c4] =
                *(const uint4*)(g_A + ABASE + (size_t)(k0 + k) * Mdim + m0 + c4);
        }
        {
            int k = tid >> 4, c4 = (tid & 15) * 4;
            *(uint4*)&Bs[k][c4] =
                *(const uint4*)(g_B + BBASE + (size_t)(k0 + k) * Ndim + n0 + c4);
        }
        __syncthreads();

        #pragma unroll
        for (int kc = 0; kc < 2; kc++) {
            const int kb = kc * 8;
            unsigned int afr[2][4];
            #pragma unroll
            for (int mi = 0; mi < 2; mi++) {
                int rb = wm*32 + mi*16 + lr;
                afr[mi][0] = As[kb + lc    ][rb    ];
                afr[mi][1] = As[kb + lc    ][rb + 8];
                afr[mi][2] = As[kb + lc + 4][rb    ];
                afr[mi][3] = As[kb + lc + 4][rb + 8];
            }
            #pragma unroll
            for (int nj = 0; nj < 4; nj++) {
                int nb = wn*32 + nj*8 + lr;
                unsigned int b0 = Bs[kb + lc    ][nb];
                unsigned int b1 = Bs[kb + lc + 4][nb];
                #pragma unroll
                for (int mi = 0; mi < 2; mi++)
                    MMA_TF32(acc[mi][nj][0], acc[mi][nj][1], acc[mi][nj][2], acc[mi][nj][3],
                             afr[mi][0], afr[mi][1], afr[mi][2], afr[mi][3], b0, b1);
            }
        }
        __syncthreads();
    }

    const float scale = 0.25f * rsqrtf((float)d);
    #pragma unroll
    for (int mi = 0; mi < 2; mi++) {
        #pragma unroll
        for (int nj = 0; nj < 4; nj++) {
            #pragma unroll
            for (int rr = 0; rr < 2; rr++) {
                int row = m0 + wm*32 + mi*16 + lr + rr*8;
                int bt = row / d, mm = row - bt * d;
                #pragma unroll
                for (int cc = 0; cc < 2; cc++) {
                    int col = n0 + wn*32 + nj*8 + lc*2 + cc;
                    int g2 = col / d, v = col - g2 * d;
                    g_TJ[(size_t)(bt*64 + g2) * DIM6c + OFF + v*d + mm] =
                        acc[mi][nj][rr*2 + cc] * scale;
                }
            }
        }
    }
}
__global__ __launch_bounds__(256) void kCgemm() {
    __shared__ unsigned int As[16][136];
    __shared__ unsigned int Bs[16][72];
    switch (blockIdx.y) {
        case 0: kCmma_body<0,0,  AB0,BB0>(As,Bs); break;
        case 1: kCmma_body<1,1,  AB1,BB1>(As,Bs); break;
        case 2: kCmma_body<2,10, AB2,BB2>(As,Bs); break;
        case 3: kCmma_body<3,35, AB3,BB3>(As,Bs); break;
        case 4: kCmma_body<4,84, AB4,BB4>(As,Bs); break;
        case 5: kCmma_body<5,165,AB5,BB5>(As,Bs); break;
        case 6: kCmma_body<6,286,AB6,BB6>(As,Bs); break;
    }
}

// ============ kDmma: out[r][i] = sum_j A[r][j] * ico[i][j], fp16 mma ========
__global__ __launch_bounds__(256) void kDmma(const float* __restrict__ x,
                                             const float* __restrict__ ico,
                                             float* __restrict__ out, int I) {
    __shared__ __half As[128][36];
    __shared__ __half Bs[64][36];
    const int r0 = blockIdx.x * 128;
    const float* Ap = (r0 < XROWS) ? (x + (size_t)r0 * DIM6c)
                                   : (g_TJ + (size_t)(r0 - XROWS) * DIM6c);
    const int tid = threadIdx.x;
    const int wid = tid >> 5, lane = tid & 31;
    const int wm = wid >> 1, wn = wid & 1;
    const int lr = lane >> 2;
    const int lc = lane & 3;
    const unsigned int* A32 = (const unsigned int*)&As[0][0];
    const unsigned int* B32 = (const unsigned int*)&Bs[0][0];

    float acc[2][4][4];
    #pragma unroll
    for (int mi = 0; mi < 2; mi++)
        #pragma unroll
        for (int nj = 0; nj < 4; nj++)
            #pragma unroll
            for (int r = 0; r < 4; r++) acc[mi][nj][r] = 0.f;

    for (int j0 = 0; j0 < 480; j0 += 32) {
        #pragma unroll
        for (int i = 0; i < 16; i++) {
            int idx = i*256 + tid;
            int r = idx >> 5, kk = idx & 31;
            int j = j0 + kk;
            As[r][kk] = (j < DIM6c) ?
                __float2half_rn(Ap[(size_t)r * DIM6c + j]) : __float2half_rn(0.f);
        }
        #pragma unroll
        for (int i = 0; i < 8; i++) {
            int idx = i*256 + tid;
            int n = idx >> 5, kk = idx & 31;
            int j = j0 + kk;
            Bs[n][kk] = (n < I && j < DIM6c) ?
                __float2half_rn(ico[(size_t)n * DIM6c + j]) : __float2half_rn(0.f);
        }
        __syncthreads();

        #pragma unroll
        for (int kc = 0; kc < 2; kc++) {
            const int w0 = kc*8 + lc;
            unsigned int afr[2][4];
            #pragma unroll
            for (int mi = 0; mi < 2; mi++) {
                int rb = wm*32 + mi*16 + lr;
                afr[mi][0] = A32[(rb    )*18 + w0    ];
                afr[mi][1] = A32[(rb + 8)*18 + w0    ];
                afr[mi][2] = A32[(rb    )*18 + w0 + 4];
                afr[mi][3] = A32[(rb + 8)*18 + w0 + 4];
            }
            #pragma unroll
            for (int nj = 0; nj < 4; nj++) {
                int nb = wn*32 + nj*8 + lr;
                unsigned int b0 = B32[nb*18 + w0    ];
                unsigned int b1 = B32[nb*18 + w0 + 4];
                #pragma unroll
                for (int mi = 0; mi < 2; mi++)
                    MMA_F16(acc[mi][nj][0], acc[mi][nj][1], acc[mi][nj][2], acc[mi][nj][3],
                            afr[mi][0], afr[mi][1], afr[mi][2], afr[mi][3], b0, b1);
            }
        }
        __syncthreads();
    }

    #pragma unroll
    for (int mi = 0; mi < 2; mi++) {
        #pragma unroll
        for (int nj = 0; nj < 4; nj++) {
            int row = r0 + wm*32 + mi*16 + lr;
            int col = wn*32 + nj*8 + lc*2;
            if (col < I) {
                out[(size_t)row * I + col] = acc[mi][nj][0];
                out[(size_t)(row + 8) * I + col] = acc[mi][nj][2];
                if (col + 1 < I) {
                    out[(size_t)row * I + col + 1] = acc[mi][nj][1];
                    out[(size_t)(row + 8) * I + col + 1] = acc[mi][nj][3];
                }
            }
        }
    }
}

extern "C" void kernel_launch(void* const* d_in, const int* in_sizes, int n_in,
                              void* d_out, int out_size) {
    const float *x = nullptr, *traj = nullptr, *w1s = nullptr, *w1v = nullptr;
    const float *Din = nullptr, *Dout = nullptr, *ico = nullptr;
    const float* w2[7] = {};
    int icoN = 60;

    for (int i = 0; i < n_in; i++) {
        int sz = in_sizes[i];
        const float* p = (const float*)d_in[i];
        switch (sz) {
            case 7454720: x    = p; break;
            case 5120:    traj = p; break;
            case 16:      w1s  = p; break;
            case 144:     w1v  = p; break;
            case 40960:   Din  = p; break;
            case 1863680: Dout = p; break;
            case 1024:    w2[0] = p; break;
            case 9216:    w2[1] = p; break;
            case 25600:   w2[2] = p; break;
            case 50176:   w2[3] = p; break;
            case 82944:   w2[4] = p; break;
            case 123904:  w2[5] = p; break;
            case 173056:  w2[6] = p; break;
            default:      ico = p; icoN = sz / DIM6c; break;
        }
    }
    float* out = (float*)d_out;

    const int SMEMB = 4 * STAGE_B;   // 73728 bytes
    cudaFuncSetAttribute(kBh, cudaFuncAttributeMaxDynamicSharedMemorySize, SMEMB);

    kH<<<MROWS/256, 256>>>(traj, w1s, w1v);
    kCvtT<<<dim3(Gc/32, NBPAD/32), 256>>>(Dout);
    kSig<<<dim3(Gc/256, MROWS/32), 256>>>(Din);
    kWt<<<dim3(676, 7), 256>>>(w2[0], w2[1], w2[2], w2[3], w2[4], w2[5], w2[6]);

    kBh<<<dim3(4, MROWS/128), 256, SMEMB>>>();

    kCgemm<<<dim3(676, 7), 256>>>();

    kDmma<<<(XROWS + TROWS)/128, 256>>>(x, ico, out, icoN);
}

// round 11
// speedup vs baseline: 1.2922x; 1.0364x over previous
#include <cuda_runtime.h>
#include <cuda_fp16.h>
#include <math.h>

#define F8c   16
#define F2c   64
#define DIM6c 455
#define PAD6  480
#define Gc    4096
#define MROWS 8192     // B*T*F8
#define BTc   512      // B*T
#define XROWS 16384    // B*H*C
#define TROWS 32768    // B*T*F2
#define NBPAD 512
#define DSCALE   256.0f
#define DUNSCALE (1.0f/256.0f)

__device__ __forceinline__ unsigned int f2tf32(float f) {
    unsigned int r;
    asm("cvt.rna.tf32.f32 %0, %1;" : "=r"(r) : "f"(f));
    return r;
}
__device__ __forceinline__ unsigned int smem_u32(const void* p) {
    return (unsigned int)__cvta_generic_to_shared(p);
}
#define CP_ASYNC16(dst, src) \
    asm volatile("cp.async.cg.shared.global [%0], [%1], 16;" :: "r"(dst), "l"(src))
#define CP_ASYNC8(dst, src) \
    asm volatile("cp.async.ca.shared.global [%0], [%1], 8;" :: "r"(dst), "l"(src))
#define CP_COMMIT()  asm volatile("cp.async.commit_group;")
#define CP_WAIT1()   asm volatile("cp.async.wait_group 1;")
#define CP_WAIT0()   asm volatile("cp.async.wait_group 0;")

#define MMA_TF32(c0,c1,c2,c3,a0,a1,a2,a3,b0,b1) \
    asm volatile("mma.sync.aligned.m16n8k8.row.col.f32.tf32.tf32.f32 " \
        "{%0,%1,%2,%3}, {%4,%5,%6,%7}, {%8,%9}, {%0,%1,%2,%3};" \
        : "+f"(c0), "+f"(c1), "+f"(c2), "+f"(c3) \
        : "r"(a0), "r"(a1), "r"(a2), "r"(a3), "r"(b0), "r"(b1))

#define MMA_F16(c0,c1,c2,c3,a0,a1,a2,a3,b0,b1) \
    asm volatile("mma.sync.aligned.m16n8k16.row.col.f32.f16.f16.f32 " \
        "{%0,%1,%2,%3}, {%4,%5,%6,%7}, {%8,%9}, {%0,%1,%2,%3};" \
        : "+f"(c0), "+f"(c1), "+f"(c2), "+f"(c3) \
        : "r"(a0), "r"(a1), "r"(a2), "r"(a3), "r"(b0), "r"(b1))

// -------- scratch --------
__device__ float          g_H  [MROWS * 10];
__device__ __half         g_sigH[(size_t)MROWS * Gc];   // fp16 sig, [m][k]
__device__ __half         g_BnH [(size_t)NBPAD * Gc];   // fp16 Dout^T * 256, [n][k]
__device__ unsigned int   g_A [8192 * 455];             // per-l A_l tf32
__device__ unsigned int   g_B [1024 * 455];             // per-l B_l tf32
__device__ __half         g_TJh[(size_t)TROWS * PAD6];  // fp16 traj455, padded
__device__ __half         g_xH [(size_t)XROWS * PAD6];  // fp16 x, padded
__device__ __half         g_icoH[64 * PAD6];            // fp16 ico, padded

#define AB0 0
#define AB1 (8192*1)
#define AB2 (8192*10)
#define AB3 (8192*35)
#define AB4 (8192*84)
#define AB5 (8192*165)
#define AB6 (8192*286)
#define BB0 0
#define BB1 (1024*1)
#define BB2 (1024*10)
#define BB3 (1024*35)
#define BB4 (1024*84)
#define BB5 (1024*165)
#define BB6 (1024*286)

// ================= kernel H =================
__global__ void kH(const float* __restrict__ traj,
                   const float* __restrict__ w1s,
                   const float* __restrict__ w1v) {
    int row = blockIdx.x * blockDim.x + threadIdx.x;
    if (row >= MROWS) return;
    int bt = row >> 4, c = row & 15;
    const float* tr = traj + bt * 10;
    float tv[9];
    #pragma unroll
    for (int q = 0; q < 9; q++) tv[q] = tr[q];
    float s = tr[9];
    float* out = g_H + row * 10;
    out[0] = s * w1s[c];
    const float inv3 = 0.57735026918962576f;
    #pragma unroll
    for (int v = 0; v < 3; v++) {
        #pragma unroll
        for (int m = 0; m < 3; m++) {
            float a = 0.f;
            #pragma unroll
            for (int u = 0; u < 3; u++)
                a += tv[u*3 + m] * w1v[c*9 + u*3 + v];
            out[1 + v*3 + m] = a * inv3;
        }
    }
}

// ============ kSig: g_sigH[m][k] = fp16(relu(H[m].Din[k])), half2 stores ====
__global__ __launch_bounds__(256) void kSig(const float* __restrict__ Din) {
    __shared__ float Hs[32][10];
    const int m0 = blockIdx.y * 32;
    const int k0 = blockIdx.x * 512 + threadIdx.x * 2;
    for (int i = threadIdx.x; i < 320; i += 256)
        Hs[i/10][i%10] = g_H[m0*10 + i];
    __syncthreads();
    float dr0[10], dr1[10];
    #pragma unroll
    for (int q = 0; q < 10; q++) { dr0[q] = Din[k0*10 + q]; dr1[q] = Din[k0*10 + 10 + q]; }
    #pragma unroll 4
    for (int m = 0; m < 32; m++) {
        float a0 = 0.f, a1 = 0.f;
        #pragma unroll
        for (int q = 0; q < 10; q++) { a0 += Hs[m][q] * dr0[q]; a1 += Hs[m][q] * dr1[q]; }
        __half2 h = __floats2half2_rn(fmaxf(a0, 0.f), fmaxf(a1, 0.f));
        *(__half2*)(g_sigH + (size_t)(m0 + m) * Gc + k0) = h;
    }
}

// ============ kCvtT: g_BnH[n][k] = fp16(Dout[k][n] * 256) ============
__global__ __launch_bounds__(256) void kCvtT(const float* __restrict__ Dout) {
    __shared__ unsigned short t[32][33];
    const int k0 = blockIdx.x * 32;
    const int n0 = blockIdx.y * 32;
    const int tx = threadIdx.x & 31, ty = threadIdx.x >> 5;
    #pragma unroll
    for (int j = 0; j < 4; j++) {
        int k = k0 + ty + j*8, n = n0 + tx;
        float v = (n < DIM6c) ? Dout[(size_t)k * DIM6c + n] * DSCALE : 0.f;
        t[ty + j*8][tx] = __half_as_ushort(__float2half_rn(v));
    }
    __syncthreads();
    #pragma unroll
    for (int j = 0; j < 4; j++) {
        int n = n0 + ty + j*8, k = k0 + tx;
        g_BnH[(size_t)n * Gc + k] = __ushort_as_half(t[tx][ty + j*8]);
    }
}

// ============ kXC: x (fp32, 455) -> g_xH (fp16, 480, zero-padded) ============
__global__ __launch_bounds__(256) void kXC(const float* __restrict__ x) {
    size_t idx = (size_t)blockIdx.x * 256 + threadIdx.x;     // over XROWS*PAD6
    int r = (int)(idx / PAD6), j = (int)(idx - (size_t)r * PAD6);
    g_xH[idx] = (j < DIM6c) ? __float2half_rn(x[(size_t)r * DIM6c + j])
                            : __float2half_rn(0.f);
}

// ============ kAux: ico -> g_icoH (padded); zero g_TJh pad columns ==========
__global__ __launch_bounds__(256) void kAux(const float* __restrict__ ico, int I) {
    int idx = blockIdx.x * 256 + threadIdx.x;
    if (idx < 64 * PAD6) {
        int n = idx / PAD6, j = idx - n * PAD6;
        g_icoH[idx] = (n < I && j < DIM6c) ?
            __float2half_rn(ico[(size_t)n * DIM6c + j]) : __float2half_rn(0.f);
    } else {
        int k = idx - 64 * PAD6;              // over TROWS*25
        if (k < TROWS * 25) {
            int r = k / 25, j = DIM6c + (k - r * 25);
            g_TJh[(size_t)r * PAD6 + j] = __float2half_rn(0.f);
        }
    }
}

// ===== scatter one C element straight into per-l tf32 A =====
__device__ __forceinline__ void scatterA(int row, int col, float val) {
    if (col >= DIM6c) return;
    unsigned int tv = f2tf32(val);
    int bt = row >> 4, f = row & 15;
    if (col < 1) {
        g_A[AB0 + f * 512 + bt] = tv;
    } else if (col < 10) {
        int r = col - 1, u = r / 3, m = r - u*3;
        g_A[AB1 + (f*3 + u) * (512*3) + bt*3 + m] = tv;
    } else if (col < 35) {
        int r = col - 10, u = r / 5, m = r - u*5;
        g_A[AB2 + (f*5 + u) * (512*5) + bt*5 + m] = tv;
    } else if (col < 84) {
        int r = col - 35, u = r / 7, m = r - u*7;
        g_A[AB3 + (f*7 + u) * (512*7) + bt*7 + m] = tv;
    } else if (col < 165) {
        int r = col - 84, u = r / 9, m = r - u*9;
        g_A[AB4 + (f*9 + u) * (512*9) + bt*9 + m] = tv;
    } else if (col < 286) {
        int r = col - 165, u = r / 11, m = r - u*11;
        g_A[AB5 + (f*11 + u) * (512*11) + bt*11 + m] = tv;
    } else {
        int r = col - 286, u = r / 13, m = r - u*13;
        g_A[AB6 + (f*13 + u) * (512*13) + bt*13 + m] = tv;
    }
}

// ============ kBh: fp16 mma GEMM. CTA 128x128, BK=64, 2-stage cp.async ====
#define STAGE_B 18432              // 128*72*2 bytes
__global__ __launch_bounds__(256) void kBh() {
    extern __shared__ __align__(16) char smb[];
    const int n0 = blockIdx.x * 128;
    const int m0 = blockIdx.y * 128;
    const int tid = threadIdx.x;
    const int wid = tid >> 5, lane = tid & 31;
    const int wm = wid >> 1, wn = wid & 1;
    const int lr = lane >> 2;
    const int lc = lane & 3;

    float acc[2][8][4];
    #pragma unroll
    for (int mi = 0; mi < 2; mi++)
        #pragma unroll
        for (int nj = 0; nj < 8; nj++)
            #pragma unroll
            for (int r = 0; r < 4; r++) acc[mi][nj][r] = 0.f;

    auto issue = [&](int buf, int k0) {
        #pragma unroll
        for (int i = 0; i < 4; i++) {
            int id = tid + i*256;
            int row = id >> 3, cc = id & 7;
            CP_ASYNC16(smem_u32(smb + buf*STAGE_B + row*144 + cc*16),
                       g_sigH + (size_t)(m0 + row) * Gc + k0 + cc*8);
            CP_ASYNC16(smem_u32(smb + 2*STAGE_B + buf*STAGE_B + row*144 + cc*16),
                       g_BnH + (size_t)(n0 + row) * Gc + k0 + cc*8);
        }
    };

    issue(0, 0);  CP_COMMIT();
    issue(1, 64); CP_COMMIT();

    const int rb0 = wm*32 + lr;
    const int NIT = Gc / 64;
    for (int it = 0; it < NIT; it++) {
        const int buf = it & 1;
        const unsigned int* A32 = (const unsigned int*)(smb + buf*STAGE_B);
        const unsigned int* B32 = (const unsigned int*)(smb + 2*STAGE_B + buf*STAGE_B);
        CP_WAIT1();
        __syncthreads();

        #pragma unroll
        for (int kc = 0; kc < 4; kc++) {
            const int w0 = kc*8 + lc;
            unsigned int afr[2][4];
            #pragma unroll
            for (int mi = 0; mi < 2; mi++) {
                int rb = rb0 + mi*16;
                afr[mi][0] = A32[(rb    )*36 + w0    ];
                afr[mi][1] = A32[(rb + 8)*36 + w0    ];
                afr[mi][2] = A32[(rb    )*36 + w0 + 4];
                afr[mi][3] = A32[(rb + 8)*36 + w0 + 4];
            }
            #pragma unroll
            for (int nj = 0; nj < 8; nj++) {
                int nb = wn*64 + nj*8 + lr;
                unsigned int b0 = B32[nb*36 + w0    ];
                unsigned int b1 = B32[nb*36 + w0 + 4];
                #pragma unroll
                for (int mi = 0; mi < 2; mi++)
                    MMA_F16(acc[mi][nj][0], acc[mi][nj][1], acc[mi][nj][2], acc[mi][nj][3],
                            afr[mi][0], afr[mi][1], afr[mi][2], afr[mi][3], b0, b1);
            }
        }
        __syncthreads();
        int nk = (it + 2) * 64;
        if (nk < Gc) issue(buf, nk);
        CP_COMMIT();
    }

    #pragma unroll
    for (int mi = 0; mi < 2; mi++) {
        #pragma unroll
        for (int nj = 0; nj < 8; nj++) {
            int row = m0 + wm*32 + mi*16 + lr;
            int col = n0 + wn*64 + nj*8 + lc*2;
            scatterA(row,     col,     acc[mi][nj][0] * DUNSCALE);
            scatterA(row,     col + 1, acc[mi][nj][1] * DUNSCALE);
            scatterA(row + 8, col,     acc[mi][nj][2] * DUNSCALE);
            scatterA(row + 8, col + 1, acc[mi][nj][3] * DUNSCALE);
        }
    }
}

// ============ kWt: g_B[l][(f*d+u)][(g2*d+v)] = tf32(w2[f][g2][u][v]) ===
template<int L, int BBASE>
__device__ __forceinline__ void kWt_body(const float* __restrict__ wl) {
    constexpr int d = 2*L + 1;
    constexpr int Ndim = 64 * d;
    int idx = blockIdx.x * 256 + threadIdx.x;
    if (idx >= 16 * d * Ndim) return;
    int k = idx / Ndim, n = idx - k * Ndim;
    int f = k / d, u = k - f * d;
    int g2 = n / d, v = n - g2 * d;
    g_B[BBASE + idx] = f2tf32(wl[((f*64 + g2) * d + u) * d + v]);
}
__global__ __launch_bounds__(256) void kWt(
    const float* w0, const float* w1, const float* w2p, const float* w3,
    const float* w4, const float* w5, const float* w6) {
    switch (blockIdx.y) {
        case 0: kWt_body<0,BB0>(w0);  break;
        case 1: kWt_body<1,BB1>(w1);  break;
        case 2: kWt_body<2,BB2>(w2p); break;
        case 3: kWt_body<3,BB3>(w3);  break;
        case 4: kWt_body<4,BB4>(w4);  break;
        case 5: kWt_body<5,BB5>(w5);  break;
        case 6: kWt_body<6,BB6>(w6);  break;
    }
}

// ============ kCgemm: per-l C = A_l @ B_l (tf32 mma.sync), write g_TJh ======
template<int L, int OFF, int ABASE, int BBASE>
__device__ __forceinline__ void kCmma_body(unsigned int (*As)[136],
                                           unsigned int (*Bs)[72]) {
    constexpr int d    = 2*L + 1;
    constexpr int Mdim = 512 * d;
    constexpr int Ndim = 64 * d;
    constexpr int K    = 16 * d;
    constexpr int TM   = Mdim / 128;
    constexpr int TN   = Ndim / 64;
    const int tile = blockIdx.x;
    if (tile >= TM * TN) return;
    const int m0 = (tile % TM) * 128;
    const int n0 = (tile / TM) * 64;
    const int tid = threadIdx.x;
    const int wid = tid >> 5, lane = tid & 31;
    const int wm = wid >> 1, wn = wid & 1;
    const int lr = lane >> 2, lc = lane & 3;

    float acc[2][4][4];
    #pragma unroll
    for (int mi = 0; mi < 2; mi++)
        #pragma unroll
        for (int nj = 0; nj < 4; nj++)
            #pragma unroll
            for (int r = 0; r < 4; r++) acc[mi][nj][r] = 0.f;

    for (int k0 = 0; k0 < K; k0 += 16) {
        #pragma unroll
        for (int i = 0; i < 2; i++) {
            int idx = tid + i*256;
            int k = idx >> 5, c4 = (idx & 31) * 4;
            *(uint4*)&As[k][c4] =
                *(const uint4*)(g_A + ABASE + (size_t)(k0 + k) * Mdim + m0 + c4);
        }
        {
            int k = tid >> 4, c4 = (tid & 15) * 4;
            *(uint4*)&Bs[k][c4] =
                *(const uint4*)(g_B + BBASE + (size_t)(k0 + k) * Ndim + n0 + c4);
        }
        __syncthreads();

        #pragma unroll
        for (int kc = 0; kc < 2; kc++) {
            const int kb = kc * 8;
            unsigned int afr[2][4];
            #pragma unroll
            for (int mi = 0; mi < 2; mi++) {
                int rb = wm*32 + mi*16 + lr;
                afr[mi][0] = As[kb + lc    ][rb    ];
                afr[mi][1] = As[kb + lc    ][rb + 8];
                afr[mi][2] = As[kb + lc + 4][rb    ];
                afr[mi][3] = As[kb + lc + 4][rb + 8];
            }
            #pragma unroll
            for (int nj = 0; nj < 4; nj++) {
                int nb = wn*32 + nj*8 + lr;
                unsigned int b0 = Bs[kb + lc    ][nb];
                unsigned int b1 = Bs[kb + lc + 4][nb];
                #pragma unroll
                for (int mi = 0; mi < 2; mi++)
                    MMA_TF32(acc[mi][nj][0], acc[mi][nj][1], acc[mi][nj][2], acc[mi][nj][3],
                             afr[mi][0], afr[mi][1], afr[mi][2], afr[mi][3], b0, b1);
            }
        }
        __syncthreads();
    }

    const float scale = 0.25f * rsqrtf((float)d);
    #pragma unroll
    for (int mi = 0; mi < 2; mi++) {
        #pragma unroll
        for (int nj = 0; nj < 4; nj++) {
            #pragma unroll
            for (int rr = 0; rr < 2; rr++) {
                int row = m0 + wm*32 + mi*16 + lr + rr*8;
                int bt = row / d, mm = row - bt * d;
                #pragma unroll
                for (int cc = 0; cc < 2; cc++) {
                    int col = n0 + wn*32 + nj*8 + lc*2 + cc;
                    int g2 = col / d, v = col - g2 * d;
                    g_TJh[(size_t)(bt*64 + g2) * PAD6 + OFF + v*d + mm] =
                        __float2half_rn(acc[mi][nj][rr*2 + cc] * scale);
                }
            }
        }
    }
}
__global__ __launch_bounds__(256) void kCgemm() {
    __shared__ unsigned int As[16][136];
    __shared__ unsigned int Bs[16][72];
    switch (blockIdx.y) {
        case 0: kCmma_body<0,0,  AB0,BB0>(As,Bs); break;
        case 1: kCmma_body<1,1,  AB1,BB1>(As,Bs); break;
        case 2: kCmma_body<2,10, AB2,BB2>(As,Bs); break;
        case 3: kCmma_body<3,35, AB3,BB3>(As,Bs); break;
        case 4: kCmma_body<4,84, AB4,BB4>(As,Bs); break;
        case 5: kCmma_body<5,165,AB5,BB5>(As,Bs); break;
        case 6: kCmma_body<6,286,AB6,BB6>(As,Bs); break;
    }
}

// ============ kDmma: fp16 mma, cp.async fills from fp16 padded sources ======
__global__ __launch_bounds__(256) void kDmma(const float* __restrict__ ico_unused,
                                             float* __restrict__ out, int I) {
    __shared__ __align__(16) __half As[128][36];
    __shared__ __align__(16) __half Bs[64][36];
    const int r0 = blockIdx.x * 128;
    const __half* Ap = (r0 < XROWS) ? (g_xH + (size_t)r0 * PAD6)
                                    : (g_TJh + (size_t)(r0 - XROWS) * PAD6);
    const int tid = threadIdx.x;
    const int wid = tid >> 5, lane = tid & 31;
    const int wm = wid >> 1, wn = wid & 1;
    const int lr = lane >> 2;
    const int lc = lane & 3;
    const unsigned int* A32 = (const unsigned int*)&As[0][0];
    const unsigned int* B32 = (const unsigned int*)&Bs[0][0];

    float acc[2][4][4];
    #pragma unroll
    for (int mi = 0; mi < 2; mi++)
        #pragma unroll
        for (int nj = 0; nj < 4; nj++)
            #pragma unroll
            for (int r = 0; r < 4; r++) acc[mi][nj][r] = 0.f;

    for (int j0 = 0; j0 < PAD6; j0 += 32) {
        // A: 128 rows x 32 halves = 8 chunks of 8B per row -> 1024 chunks
        #pragma unroll
        for (int i = 0; i < 4; i++) {
            int id = tid + i*256;
            int r = id >> 3, ch = id & 7;
            CP_ASYNC8(smem_u32((char*)&As[0][0] + r*72 + ch*8),
                      Ap + (size_t)r * PAD6 + j0 + ch*4);
        }
        // B: 64 rows x 32 halves -> 512 chunks
        #pragma unroll
        for (int i = 0; i < 2; i++) {
            int id = tid + i*256;
            int n = id >> 3, ch = id & 7;
            CP_ASYNC8(smem_u32((char*)&Bs[0][0] + n*72 + ch*8),
                      g_icoH + (size_t)n * PAD6 + j0 + ch*4);
        }
        CP_COMMIT();
        CP_WAIT0();
        __syncthreads();

        #pragma unroll
        for (int kc = 0; kc < 2; kc++) {
            const int w0 = kc*8 + lc;
            unsigned int afr[2][4];
            #pragma unroll
            for (int mi = 0; mi < 2; mi++) {
                int rb = wm*32 + mi*16 + lr;
                afr[mi][0] = A32[(rb    )*18 + w0    ];
                afr[mi][1] = A32[(rb + 8)*18 + w0    ];
                afr[mi][2] = A32[(rb    )*18 + w0 + 4];
                afr[mi][3] = A32[(rb + 8)*18 + w0 + 4];
            }
            #pragma unroll
            for (int nj = 0; nj < 4; nj++) {
                int nb = wn*32 + nj*8 + lr;
                unsigned int b0 = B32[nb*18 + w0    ];
                unsigned int b1 = B32[nb*18 + w0 + 4];
                #pragma unroll
                for (int mi = 0; mi < 2; mi++)
                    MMA_F16(acc[mi][nj][0], acc[mi][nj][1], acc[mi][nj][2], acc[mi][nj][3],
                            afr[mi][0], afr[mi][1], afr[mi][2], afr[mi][3], b0, b1);
            }
        }
        __syncthreads();
    }

    #pragma unroll
    for (int mi = 0; mi < 2; mi++) {
        #pragma unroll
        for (int nj = 0; nj < 4; nj++) {
            int row = r0 + wm*32 + mi*16 + lr;
            int col = wn*32 + nj*8 + lc*2;
            if (col < I) {
                out[(size_t)row * I + col] = acc[mi][nj][0];
                out[(size_t)(row + 8) * I + col] = acc[mi][nj][2];
                if (col + 1 < I) {
                    out[(size_t)row * I + col + 1] = acc[mi][nj][1];
                    out[(size_t)(row + 8) * I + col + 1] = acc[mi][nj][3];
                }
            }
        }
    }
}

extern "C" void kernel_launch(void* const* d_in, const int* in_sizes, int n_in,
                              void* d_out, int out_size) {
    const float *x = nullptr, *traj = nullptr, *w1s = nullptr, *w1v = nullptr;
    const float *Din = nullptr, *Dout = nullptr, *ico = nullptr;
    const float* w2[7] = {};
    int icoN = 60;

    for (int i = 0; i < n_in; i++) {
        int sz = in_sizes[i];
        const float* p = (const float*)d_in[i];
        switch (sz) {
            case 7454720: x    = p; break;
            case 5120:    traj = p; break;
            case 16:      w1s  = p; break;
            case 144:     w1v  = p; break;
            case 40960:   Din  = p; break;
            case 1863680: Dout = p; break;
            case 1024:    w2[0] = p; break;
            case 9216:    w2[1] = p; break;
            case 25600:   w2[2] = p; break;
            case 50176:   w2[3] = p; break;
            case 82944:   w2[4] = p; break;
            case 123904:  w2[5] = p; break;
            case 173056:  w2[6] = p; break;
            default:      ico = p; icoN = sz / DIM6c; break;
        }
    }
    float* out = (float*)d_out;

    const int SMEMB = 4 * STAGE_B;   // 73728 bytes
    cudaFuncSetAttribute(kBh, cudaFuncAttributeMaxDynamicSharedMemorySize, SMEMB);

    kH<<<MROWS/256, 256>>>(traj, w1s, w1v);
    kCvtT<<<dim3(Gc/32, NBPAD/32), 256>>>(Dout);
    kSig<<<dim3(Gc/512, MROWS/32), 256>>>(Din);
    kWt<<<dim3(676, 7), 256>>>(w2[0], w2[1], w2[2], w2[3], w2[4], w2[5], w2[6]);
    kXC<<<(XROWS * PAD6) / 256, 256>>>(x);
    kAux<<<(64 * PAD6 + TROWS * 25 + 255) / 256, 256>>>(ico, icoN);

    kBh<<<dim3(4, MROWS/128), 256, SMEMB>>>();

    kCgemm<<<dim3(676, 7), 256>>>();

    kDmma<<<(XROWS + TROWS)/128, 256>>>(nullptr, out, icoN);
}

// round 12
// speedup vs baseline: 1.3303x; 1.0295x over previous
#include <cuda_runtime.h>
#include <cuda_fp16.h>
#include <math.h>

#define F8c   16
#define F2c   64
#define DIM6c 455
#define PAD6  480
#define Gc    4096
#define MROWS 8192     // B*T*F8
#define BTc   512      // B*T
#define XROWS 16384    // B*H*C
#define TROWS 32768    // B*T*F2
#define NBPAD 512
#define DSCALE   256.0f
#define DUNSCALE (1.0f/256.0f)

__device__ __forceinline__ unsigned int f2tf32(float f) {
    unsigned int r;
    asm("cvt.rna.tf32.f32 %0, %1;" : "=r"(r) : "f"(f));
    return r;
}
__device__ __forceinline__ unsigned int smem_u32(const void* p) {
    return (unsigned int)__cvta_generic_to_shared(p);
}
#define CP_ASYNC16(dst, src) \
    asm volatile("cp.async.cg.shared.global [%0], [%1], 16;" :: "r"(dst), "l"(src))
#define CP_ASYNC8(dst, src) \
    asm volatile("cp.async.ca.shared.global [%0], [%1], 8;" :: "r"(dst), "l"(src))
#define CP_COMMIT()  asm volatile("cp.async.commit_group;")
#define CP_WAIT1()   asm volatile("cp.async.wait_group 1;")
#define CP_WAIT0()   asm volatile("cp.async.wait_group 0;")

#define MMA_TF32(c0,c1,c2,c3,a0,a1,a2,a3,b0,b1) \
    asm volatile("mma.sync.aligned.m16n8k8.row.col.f32.tf32.tf32.f32 " \
        "{%0,%1,%2,%3}, {%4,%5,%6,%7}, {%8,%9}, {%0,%1,%2,%3};" \
        : "+f"(c0), "+f"(c1), "+f"(c2), "+f"(c3) \
        : "r"(a0), "r"(a1), "r"(a2), "r"(a3), "r"(b0), "r"(b1))

#define MMA_F16(c0,c1,c2,c3,a0,a1,a2,a3,b0,b1) \
    asm volatile("mma.sync.aligned.m16n8k16.row.col.f32.f16.f16.f32 " \
        "{%0,%1,%2,%3}, {%4,%5,%6,%7}, {%8,%9}, {%0,%1,%2,%3};" \
        : "+f"(c0), "+f"(c1), "+f"(c2), "+f"(c3) \
        : "r"(a0), "r"(a1), "r"(a2), "r"(a3), "r"(b0), "r"(b1))

#define LDSM4(r0,r1,r2,r3,addr) \
    asm volatile("ldmatrix.sync.aligned.m8n8.x4.shared.b16 {%0,%1,%2,%3}, [%4];" \
        : "=r"(r0), "=r"(r1), "=r"(r2), "=r"(r3) : "r"(addr))

// -------- scratch --------
__device__ float          g_H  [MROWS * 10];
__device__ __half         g_sigH[(size_t)MROWS * Gc];   // fp16 sig, [m][k]
__device__ __half         g_BnH [(size_t)NBPAD * Gc];   // fp16 Dout^T * 256, [n][k]
__device__ unsigned int   g_A [8192 * 455];             // per-l A_l tf32
__device__ unsigned int   g_B [1024 * 455];             // per-l B_l tf32
__device__ __half         g_TJh[(size_t)TROWS * PAD6];  // fp16 traj455, padded
__device__ __half         g_xH [(size_t)XROWS * PAD6];  // fp16 x, padded
__device__ __half         g_icoH[64 * PAD6];            // fp16 ico, padded

#define AB0 0
#define AB1 (8192*1)
#define AB2 (8192*10)
#define AB3 (8192*35)
#define AB4 (8192*84)
#define AB5 (8192*165)
#define AB6 (8192*286)
#define BB0 0
#define BB1 (1024*1)
#define BB2 (1024*10)
#define BB3 (1024*35)
#define BB4 (1024*84)
#define BB5 (1024*165)
#define BB6 (1024*286)

// ================= kernel H =================
__global__ void kH(const float* __restrict__ traj,
                   const float* __restrict__ w1s,
                   const float* __restrict__ w1v) {
    int row = blockIdx.x * blockDim.x + threadIdx.x;
    if (row >= MROWS) return;
    int bt = row >> 4, c = row & 15;
    const float* tr = traj + bt * 10;
    float tv[9];
    #pragma unroll
    for (int q = 0; q < 9; q++) tv[q] = tr[q];
    float s = tr[9];
    float* out = g_H + row * 10;
    out[0] = s * w1s[c];
    const float inv3 = 0.57735026918962576f;
    #pragma unroll
    for (int v = 0; v < 3; v++) {
        #pragma unroll
        for (int m = 0; m < 3; m++) {
            float a = 0.f;
            #pragma unroll
            for (int u = 0; u < 3; u++)
                a += tv[u*3 + m] * w1v[c*9 + u*3 + v];
            out[1 + v*3 + m] = a * inv3;
        }
    }
}

// ============ kSig: g_sigH[m][k] = fp16(relu(H[m].Din[k])), half2 stores ====
__global__ __launch_bounds__(256) void kSig(const float* __restrict__ Din) {
    __shared__ float Hs[32][10];
    const int m0 = blockIdx.y * 32;
    const int k0 = blockIdx.x * 512 + threadIdx.x * 2;
    for (int i = threadIdx.x; i < 320; i += 256)
        Hs[i/10][i%10] = g_H[m0*10 + i];
    __syncthreads();
    float dr0[10], dr1[10];
    #pragma unroll
    for (int q = 0; q < 10; q++) { dr0[q] = Din[k0*10 + q]; dr1[q] = Din[k0*10 + 10 + q]; }
    #pragma unroll 4
    for (int m = 0; m < 32; m++) {
        float a0 = 0.f, a1 = 0.f;
        #pragma unroll
        for (int q = 0; q < 10; q++) { a0 += Hs[m][q] * dr0[q]; a1 += Hs[m][q] * dr1[q]; }
        __half2 h = __floats2half2_rn(fmaxf(a0, 0.f), fmaxf(a1, 0.f));
        *(__half2*)(g_sigH + (size_t)(m0 + m) * Gc + k0) = h;
    }
}

// ============ kCvtT: g_BnH[n][k] = fp16(Dout[k][n] * 256) ============
__global__ __launch_bounds__(256) void kCvtT(const float* __restrict__ Dout) {
    __shared__ unsigned short t[32][33];
    const int k0 = blockIdx.x * 32;
    const int n0 = blockIdx.y * 32;
    const int tx = threadIdx.x & 31, ty = threadIdx.x >> 5;
    #pragma unroll
    for (int j = 0; j < 4; j++) {
        int k = k0 + ty + j*8, n = n0 + tx;
        float v = (n < DIM6c) ? Dout[(size_t)k * DIM6c + n] * DSCALE : 0.f;
        t[ty + j*8][tx] = __half_as_ushort(__float2half_rn(v));
    }
    __syncthreads();
    #pragma unroll
    for (int j = 0; j < 4; j++) {
        int n = n0 + ty + j*8, k = k0 + tx;
        g_BnH[(size_t)n * Gc + k] = __ushort_as_half(t[tx][ty + j*8]);
    }
}

// ============ kXC: x (fp32, 455) -> g_xH (fp16, 480, zero-padded) ============
__global__ __launch_bounds__(256) void kXC(const float* __restrict__ x) {
    size_t idx = (size_t)blockIdx.x * 256 + threadIdx.x;     // over XROWS*PAD6
    int r = (int)(idx / PAD6), j = (int)(idx - (size_t)r * PAD6);
    g_xH[idx] = (j < DIM6c) ? __float2half_rn(x[(size_t)r * DIM6c + j])
                            : __float2half_rn(0.f);
}

// ============ kAux: ico -> g_icoH (padded); zero g_TJh pad columns ==========
__global__ __launch_bounds__(256) void kAux(const float* __restrict__ ico, int I) {
    int idx = blockIdx.x * 256 + threadIdx.x;
    if (idx < 64 * PAD6) {
        int n = idx / PAD6, j = idx - n * PAD6;
        g_icoH[idx] = (n < I && j < DIM6c) ?
            __float2half_rn(ico[(size_t)n * DIM6c + j]) : __float2half_rn(0.f);
    } else {
        int k = idx - 64 * PAD6;              // over TROWS*25
        if (k < TROWS * 25) {
            int r = k / 25, j = DIM6c + (k - r * 25);
            g_TJh[(size_t)r * PAD6 + j] = __float2half_rn(0.f);
        }
    }
}

// ===== scatter one C element straight into per-l tf32 A =====
__device__ __forceinline__ void scatterA(int row, int col, float val) {
    if (col >= DIM6c) return;
    unsigned int tv = f2tf32(val);
    int bt = row >> 4, f = row & 15;
    if (col < 1) {
        g_A[AB0 + f * 512 + bt] = tv;
    } else if (col < 10) {
        int r = col - 1, u = r / 3, m = r - u*3;
        g_A[AB1 + (f*3 + u) * (512*3) + bt*3 + m] = tv;
    } else if (col < 35) {
        int r = col - 10, u = r / 5, m = r - u*5;
        g_A[AB2 + (f*5 + u) * (512*5) + bt*5 + m] = tv;
    } else if (col < 84) {
        int r = col - 35, u = r / 7, m = r - u*7;
        g_A[AB3 + (f*7 + u) * (512*7) + bt*7 + m] = tv;
    } else if (col < 165) {
        int r = col - 84, u = r / 9, m = r - u*9;
        g_A[AB4 + (f*9 + u) * (512*9) + bt*9 + m] = tv;
    } else if (col < 286) {
        int r = col - 165, u = r / 11, m = r - u*11;
        g_A[AB5 + (f*11 + u) * (512*11) + bt*11 + m] = tv;
    } else {
        int r = col - 286, u = r / 13, m = r - u*13;
        g_A[AB6 + (f*13 + u) * (512*13) + bt*13 + m] = tv;
    }
}

// ============ kBh: fp16 mma GEMM with ldmatrix. CTA 128x128, BK=64 ====
#define STAGE_B 18432              // 128*72*2 bytes
__global__ __launch_bounds__(256) void kBh() {
    extern __shared__ __align__(16) char smb[];
    const int n0 = blockIdx.x * 128;
    const int m0 = blockIdx.y * 128;
    const int tid = threadIdx.x;
    const int wid = tid >> 5, lane = tid & 31;
    const int wm = wid >> 1, wn = wid & 1;
    const int lr = lane >> 2;
    const int lc = lane & 3;

    float acc[2][8][4];
    #pragma unroll
    for (int mi = 0; mi < 2; mi++)
        #pragma unroll
        for (int nj = 0; nj < 8; nj++)
            #pragma unroll
            for (int r = 0; r < 4; r++) acc[mi][nj][r] = 0.f;

    auto issue = [&](int buf, int k0) {
        #pragma unroll
        for (int i = 0; i < 4; i++) {
            int id = tid + i*256;
            int row = id >> 3, cc = id & 7;
            CP_ASYNC16(smem_u32(smb + buf*STAGE_B + row*144 + cc*16),
                       g_sigH + (size_t)(m0 + row) * Gc + k0 + cc*8);
            CP_ASYNC16(smem_u32(smb + 2*STAGE_B + buf*STAGE_B + row*144 + cc*16),
                       g_BnH + (size_t)(n0 + row) * Gc + k0 + cc*8);
        }
    };

    issue(0, 0);  CP_COMMIT();
    issue(1, 64); CP_COMMIT();

    // ldmatrix lane addressing (validated in R9: rel_err matched)
    const int a_row_in = (lane & 15);            // row within 16-row frag
    const int a_koff   = (lane >> 4) << 4;       // 0 or 16 bytes
    const int b_row_in = ((lane >> 4) << 3) + (lane & 7);
    const int b_koff   = ((lane >> 3) & 1) << 4;

    const int NIT = Gc / 64;
    for (int it = 0; it < NIT; it++) {
        const int buf = it & 1;
        const unsigned int Abase = smem_u32(smb + buf*STAGE_B);
        const unsigned int Bbase = smem_u32(smb + 2*STAGE_B + buf*STAGE_B);
        CP_WAIT1();
        __syncthreads();

        #pragma unroll
        for (int kc = 0; kc < 4; kc++) {
            unsigned int afr[2][4];
            #pragma unroll
            for (int mi = 0; mi < 2; mi++) {
                int row = wm*32 + mi*16 + a_row_in;
                LDSM4(afr[mi][0], afr[mi][1], afr[mi][2], afr[mi][3],
                      Abase + row*144 + kc*32 + a_koff);
            }
            unsigned int bfr[8][2];
            #pragma unroll
            for (int njp = 0; njp < 4; njp++) {
                int row = wn*64 + njp*16 + b_row_in;
                LDSM4(bfr[2*njp][0], bfr[2*njp][1], bfr[2*njp+1][0], bfr[2*njp+1][1],
                      Bbase + row*144 + kc*32 + b_koff);
            }
            #pragma unroll
            for (int nj = 0; nj < 8; nj++)
                #pragma unroll
                for (int mi = 0; mi < 2; mi++)
                    MMA_F16(acc[mi][nj][0], acc[mi][nj][1], acc[mi][nj][2], acc[mi][nj][3],
                            afr[mi][0], afr[mi][1], afr[mi][2], afr[mi][3],
                            bfr[nj][0], bfr[nj][1]);
        }
        __syncthreads();
        int nk = (it + 2) * 64;
        if (nk < Gc) issue(buf, nk);
        CP_COMMIT();
    }

    #pragma unroll
    for (int mi = 0; mi < 2; mi++) {
        #pragma unroll
        for (int nj = 0; nj < 8; nj++) {
            int row = m0 + wm*32 + mi*16 + lr;
            int col = n0 + wn*64 + nj*8 + lc*2;
            scatterA(row,     col,     acc[mi][nj][0] * DUNSCALE);
            scatterA(row,     col + 1, acc[mi][nj][1] * DUNSCALE);
            scatterA(row + 8, col,     acc[mi][nj][2] * DUNSCALE);
            scatterA(row + 8, col + 1, acc[mi][nj][3] * DUNSCALE);
        }
    }
}

// ============ kWt: g_B[l][(f*d+u)][(g2*d+v)] = tf32(w2[f][g2][u][v]) ===
template<int L, int BBASE>
__device__ __forceinline__ void kWt_body(const float* __restrict__ wl) {
    constexpr int d = 2*L + 1;
    constexpr int Ndim = 64 * d;
    int idx = blockIdx.x * 256 + threadIdx.x;
    if (idx >= 16 * d * Ndim) return;
    int k = idx / Ndim, n = idx - k * Ndim;
    int f = k / d, u = k - f * d;
    int g2 = n / d, v = n - g2 * d;
    g_B[BBASE + idx] = f2tf32(wl[((f*64 + g2) * d + u) * d + v]);
}
__global__ __launch_bounds__(256) void kWt(
    const float* w0, const float* w1, const float* w2p, const float* w3,
    const float* w4, const float* w5, const float* w6) {
    switch (blockIdx.y) {
        case 0: kWt_body<0,BB0>(w0);  break;
        case 1: kWt_body<1,BB1>(w1);  break;
        case 2: kWt_body<2,BB2>(w2p); break;
        case 3: kWt_body<3,BB3>(w3);  break;
        case 4: kWt_body<4,BB4>(w4);  break;
        case 5: kWt_body<5,BB5>(w5);  break;
        case 6: kWt_body<6,BB6>(w6);  break;
    }
}

// ============ kCgemm: per-l C = A_l @ B_l (tf32 mma.sync), write g_TJh ======
template<int L, int OFF, int ABASE, int BBASE>
__device__ __forceinline__ void kCmma_body(unsigned int (*As)[136],
                                           unsigned int (*Bs)[72]) {
    constexpr int d    = 2*L + 1;
    constexpr int Mdim = 512 * d;
    constexpr int Ndim = 64 * d;
    constexpr int K    = 16 * d;
    constexpr int TM   = Mdim / 128;
    constexpr int TN   = Ndim / 64;
    const int tile = blockIdx.x;
    if (tile >= TM * TN) return;
    const int m0 = (tile % TM) * 128;
    const int n0 = (tile / TM) * 64;
    const int tid = threadIdx.x;
    const int wid = tid >> 5, lane = tid & 31;
    const int wm = wid >> 1, wn = wid & 1;
    const int lr = lane >> 2, lc = lane & 3;

    float acc[2][4][4];
    #pragma unroll
    for (int mi = 0; mi < 2; mi++)
        #pragma unroll
        for (int nj = 0; nj < 4; nj++)
            #pragma unroll
            for (int r = 0; r < 4; r++) acc[mi][nj][r] = 0.f;

    for (int k0 = 0; k0 < K; k0 += 16) {
        #pragma unroll
        for (int i = 0; i < 2; i++) {
            int idx = tid + i*256;
            int k = idx >> 5, c4 = (idx & 31) * 4;
            *(uint4*)&As[k][c4] =
                *(const uint4*)(g_A + ABASE + (size_t)(k0 + k) * Mdim + m0 + c4);
        }
        {
            int k = tid >> 4, c4 = (tid & 15) * 4;
            *(uint4*)&Bs[k][c4] =
                *(const uint4*)(g_B + BBASE + (size_t)(k0 + k) * Ndim + n0 + c4);
        }
        __syncthreads();

        #pragma unroll
        for (int kc = 0; kc < 2; kc++) {
            const int kb = kc * 8;
            unsigned int afr[2][4];
            #pragma unroll
            for (int mi = 0; mi < 2; mi++) {
                int rb = wm*32 + mi*16 + lr;
                afr[mi][0] = As[kb + lc    ][rb    ];
                afr[mi][1] = As[kb + lc    ][rb + 8];
                afr[mi][2] = As[kb + lc + 4][rb    ];
                afr[mi][3] = As[kb + lc + 4][rb + 8];
            }
            #pragma unroll
            for (int nj = 0; nj < 4; nj++) {
                int nb = wn*32 + nj*8 + lr;
                unsigned int b0 = Bs[kb + lc    ][nb];
                unsigned int b1 = Bs[kb + lc + 4][nb];
                #pragma unroll
                for (int mi = 0; mi < 2; mi++)
                    MMA_TF32(acc[mi][nj][0], acc[mi][nj][1], acc[mi][nj][2], acc[mi][nj][3],
                             afr[mi][0], afr[mi][1], afr[mi][2], afr[mi][3], b0, b1);
            }
        }
        __syncthreads();
    }

    const float scale = 0.25f * rsqrtf((float)d);
    #pragma unroll
    for (int mi = 0; mi < 2; mi++) {
        #pragma unroll
        for (int nj = 0; nj < 4; nj++) {
            #pragma unroll
            for (int rr = 0; rr < 2; rr++) {
                int row = m0 + wm*32 + mi*16 + lr + rr*8;
                int bt = row / d, mm = row - bt * d;
                #pragma unroll
                for (int cc = 0; cc < 2; cc++) {
                    int col = n0 + wn*32 + nj*8 + lc*2 + cc;
                    int g2 = col / d, v = col - g2 * d;
                    g_TJh[(size_t)(bt*64 + g2) * PAD6 + OFF + v*d + mm] =
                        __float2half_rn(acc[mi][nj][rr*2 + cc] * scale);
                }
            }
        }
    }
}
__global__ __launch_bounds__(256) void kCgemm() {
    __shared__ unsigned int As[16][136];
    __shared__ unsigned int Bs[16][72];
    switch (blockIdx.y) {
        case 0: kCmma_body<0,0,  AB0,BB0>(As,Bs); break;
        case 1: kCmma_body<1,1,  AB1,BB1>(As,Bs); break;
        case 2: kCmma_body<2,10, AB2,BB2>(As,Bs); break;
        case 3: kCmma_body<3,35, AB3,BB3>(As,Bs); break;
        case 4: kCmma_body<4,84, AB4,BB4>(As,Bs); break;
        case 5: kCmma_body<5,165,AB5,BB5>(As,Bs); break;
        case 6: kCmma_body<6,286,AB6,BB6>(As,Bs); break;
    }
}

// ============ kDmma: fp16 mma, cp.async fills from fp16 padded sources ======
__global__ __launch_bounds__(256) void kDmma(const float* __restrict__ ico_unused,
                                             float* __restrict__ out, int I) {
    __shared__ __align__(16) __half As[128][36];
    __shared__ __align__(16) __half Bs[64][36];
    const int r0 = blockIdx.x * 128;
    const __half* Ap = (r0 < XROWS) ? (g_xH + (size_t)r0 * PAD6)
                                    : (g_TJh + (size_t)(r0 - XROWS) * PAD6);
    const int tid = threadIdx.x;
    const int wid = tid >> 5, lane = tid & 31;
    const int wm = wid >> 1, wn = wid & 1;
    const int lr = lane >> 2;
    const int lc = lane & 3;
    const unsigned int* A32 = (const unsigned int*)&As[0][0];
    const unsigned int* B32 = (const unsigned int*)&Bs[0][0];

    float acc[2][4][4];
    #pragma unroll
    for (int mi = 0; mi < 2; mi++)
        #pragma unroll
        for (int nj = 0; nj < 4; nj++)
            #pragma unroll
            for (int r = 0; r < 4; r++) acc[mi][nj][r] = 0.f;

    for (int j0 = 0; j0 < PAD6; j0 += 32) {
        #pragma unroll
        for (int i = 0; i < 4; i++) {
            int id = tid + i*256;
            int r = id >> 3, ch = id & 7;
            CP_ASYNC8(smem_u32((char*)&As[0][0] + r*72 + ch*8),
                      Ap + (size_t)r * PAD6 + j0 + ch*4);
        }
        #pragma unroll
        for (int i = 0; i < 2; i++) {
            int id = tid + i*256;
            int n = id >> 3, ch = id & 7;
            CP_ASYNC8(smem_u32((char*)&Bs[0][0] + n*72 + ch*8),
                      g_icoH + (size_t)n * PAD6 + j0 + ch*4);
        }
        CP_COMMIT();
        CP_WAIT0();
        __syncthreads();

        #pragma unroll
        for (int kc = 0; kc < 2; kc++) {
            const int w0 = kc*8 + lc;
            unsigned int afr[2][4];
            #pragma unroll
            for (int mi = 0; mi < 2; mi++) {
                int rb = wm*32 + mi*16 + lr;
                afr[mi][0] = A32[(rb    )*18 + w0    ];
                afr[mi][1] = A32[(rb + 8)*18 + w0    ];
                afr[mi][2] = A32[(rb    )*18 + w0 + 4];
                afr[mi][3] = A32[(rb + 8)*18 + w0 + 4];
            }
            #pragma unroll
            for (int nj = 0; nj < 4; nj++) {
                int nb = wn*32 + nj*8 + lr;
                unsigned int b0 = B32[nb*18 + w0    ];
                unsigned int b1 = B32[nb*18 + w0 + 4];
                #pragma unroll
                for (int mi = 0; mi < 2; mi++)
                    MMA_F16(acc[mi][nj][0], acc[mi][nj][1], acc[mi][nj][2], acc[mi][nj][3],
                            afr[mi][0], afr[mi][1], afr[mi][2], afr[mi][3], b0, b1);
            }
        }
        __syncthreads();
    }

    #pragma unroll
    for (int mi = 0; mi < 2; mi++) {
        #pragma unroll
        for (int nj = 0; nj < 4; nj++) {
            int row = r0 + wm*32 + mi*16 + lr;
            int col = wn*32 + nj*8 + lc*2;
            if (col < I) {
                out[(size_t)row * I + col] = acc[mi][nj][0];
                out[(size_t)(row + 8) * I + col] = acc[mi][nj][2];
                if (col + 1 < I) {
                    out[(size_t)row * I + col + 1] = acc[mi][nj][1];
                    out[(size_t)(row + 8) * I + col + 1] = acc[mi][nj][3];
                }
            }
        }
    }
}

extern "C" void kernel_launch(void* const* d_in, const int* in_sizes, int n_in,
                              void* d_out, int out_size) {
    const float *x = nullptr, *traj = nullptr, *w1s = nullptr, *w1v = nullptr;
    const float *Din = nullptr, *Dout = nullptr, *ico = nullptr;
    const float* w2[7] = {};
    int icoN = 60;

    for (int i = 0; i < n_in; i++) {
        int sz = in_sizes[i];
        const float* p = (const float*)d_in[i];
        switch (sz) {
            case 7454720: x    = p; break;
            case 5120:    traj = p; break;
            case 16:      w1s  = p; break;
            case 144:     w1v  = p; break;
            case 40960:   Din  = p; break;
            case 1863680: Dout = p; break;
            case 1024:    w2[0] = p; break;
            case 9216:    w2[1] = p; break;
            case 25600:   w2[2] = p; break;
            case 50176:   w2[3] = p; break;
            case 82944:   w2[4] = p; break;
            case 123904:  w2[5] = p; break;
            case 173056:  w2[6] = p; break;
            default:      ico = p; icoN = sz / DIM6c; break;
        }
    }
    float* out = (float*)d_out;

    const int SMEMB = 4 * STAGE_B;   // 73728 bytes
    cudaFuncSetAttribute(kBh, cudaFuncAttributeMaxDynamicSharedMemorySize, SMEMB);

    kH<<<MROWS/256, 256>>>(traj, w1s, w1v);
    kCvtT<<<dim3(Gc/32, NBPAD/32), 256>>>(Dout);
    kSig<<<dim3(Gc/512, MROWS/32), 256>>>(Din);
    kWt<<<dim3(676, 7), 256>>>(w2[0], w2[1], w2[2], w2[3], w2[4], w2[5], w2[6]);
    kXC<<<(XROWS * PAD6) / 256, 256>>>(x);
    kAux<<<(64 * PAD6 + TROWS * 25 + 255) / 256, 256>>>(ico, icoN);

    kBh<<<dim3(4, MROWS/128), 256, SMEMB>>>();

    kCgemm<<<dim3(676, 7), 256>>>();

    kDmma<<<(XROWS + TROWS)/128, 256>>>(nullptr, out, icoN);
}

// round 13
// speedup vs baseline: 1.4457x; 1.0868x over previous
#include <cuda_runtime.h>
#include <cuda_fp16.h>
#include <math.h>

#define F8c   16
#define F2c   64
#define DIM6c 455
#define PAD6  480
#define Gc    4096
#define MROWS 8192     // B*T*F8
#define BTc   512      // B*T
#define XROWS 16384    // B*H*C
#define TROWS 32768    // B*T*F2
#define NBPAD 512
#define DSCALE   256.0f
#define DUNSCALE (1.0f/256.0f)

__device__ __forceinline__ unsigned int f2tf32(float f) {
    unsigned int r;
    asm("cvt.rna.tf32.f32 %0, %1;" : "=r"(r) : "f"(f));
    return r;
}
__device__ __forceinline__ unsigned int smem_u32(const void* p) {
    return (unsigned int)__cvta_generic_to_shared(p);
}
#define CP_ASYNC16(dst, src) \
    asm volatile("cp.async.cg.shared.global [%0], [%1], 16;" :: "r"(dst), "l"(src))
#define CP_ASYNC8(dst, src) \
    asm volatile("cp.async.ca.shared.global [%0], [%1], 8;" :: "r"(dst), "l"(src))
#define CP_COMMIT()  asm volatile("cp.async.commit_group;")
#define CP_WAIT1()   asm volatile("cp.async.wait_group 1;")
#define CP_WAIT0()   asm volatile("cp.async.wait_group 0;")

#define MMA_TF32(c0,c1,c2,c3,a0,a1,a2,a3,b0,b1) \
    asm volatile("mma.sync.aligned.m16n8k8.row.col.f32.tf32.tf32.f32 " \
        "{%0,%1,%2,%3}, {%4,%5,%6,%7}, {%8,%9}, {%0,%1,%2,%3};" \
        : "+f"(c0), "+f"(c1), "+f"(c2), "+f"(c3) \
        : "r"(a0), "r"(a1), "r"(a2), "r"(a3), "r"(b0), "r"(b1))

#define MMA_F16(c0,c1,c2,c3,a0,a1,a2,a3,b0,b1) \
    asm volatile("mma.sync.aligned.m16n8k16.row.col.f32.f16.f16.f32 " \
        "{%0,%1,%2,%3}, {%4,%5,%6,%7}, {%8,%9}, {%0,%1,%2,%3};" \
        : "+f"(c0), "+f"(c1), "+f"(c2), "+f"(c3) \
        : "r"(a0), "r"(a1), "r"(a2), "r"(a3), "r"(b0), "r"(b1))

#define LDSM4(r0,r1,r2,r3,addr) \
    asm volatile("ldmatrix.sync.aligned.m8n8.x4.shared.b16 {%0,%1,%2,%3}, [%4];" \
        : "=r"(r0), "=r"(r1), "=r"(r2), "=r"(r3) : "r"(addr))

// -------- scratch --------
__device__ float          g_H  [MROWS * 10];
__device__ __half         g_sigH[(size_t)MROWS * Gc];   // fp16 sig, [m][k]
__device__ __half         g_BnH [(size_t)NBPAD * Gc];   // fp16 Dout^T * 256, [n][k]
__device__ unsigned int   g_A [8192 * 455];             // per-l A_l tf32
__device__ unsigned int   g_B [1024 * 455];             // per-l B_l tf32
__device__ __half         g_TJh[(size_t)TROWS * PAD6];  // fp16 traj455, padded
__device__ __half         g_xH [(size_t)XROWS * PAD6];  // fp16 x, padded
__device__ __half         g_icoH[64 * PAD6];            // fp16 ico, padded

#define AB0 0
#define AB1 (8192*1)
#define AB2 (8192*10)
#define AB3 (8192*35)
#define AB4 (8192*84)
#define AB5 (8192*165)
#define AB6 (8192*286)
#define BB0 0
#define BB1 (1024*1)
#define BB2 (1024*10)
#define BB3 (1024*35)
#define BB4 (1024*84)
#define BB5 (1024*165)
#define BB6 (1024*286)

// ======================= kPrep bodies =======================
__device__ __forceinline__ void kH_body(const float* __restrict__ traj,
                                        const float* __restrict__ w1s,
                                        const float* __restrict__ w1v,
                                        int b, int tid) {
    int row = b * 256 + tid;
    if (row >= MROWS) return;
    int bt = row >> 4, c = row & 15;
    const float* tr = traj + bt * 10;
    float tv[9];
    #pragma unroll
    for (int q = 0; q < 9; q++) tv[q] = tr[q];
    float s = tr[9];
    float* out = g_H + row * 10;
    out[0] = s * w1s[c];
    const float inv3 = 0.57735026918962576f;
    #pragma unroll
    for (int v = 0; v < 3; v++) {
        #pragma unroll
        for (int m = 0; m < 3; m++) {
            float a = 0.f;
            #pragma unroll
            for (int u = 0; u < 3; u++)
                a += tv[u*3 + m] * w1v[c*9 + u*3 + v];
            out[1 + v*3 + m] = a * inv3;
        }
    }
}

__device__ __forceinline__ void kCvtT_body(const float* __restrict__ Dout,
                                           unsigned short (*t)[33], int b, int tidx) {
    const int k0 = (b & 127) * 32;
    const int n0 = (b >> 7) * 32;
    const int tx = tidx & 31, ty = tidx >> 5;
    #pragma unroll
    for (int j = 0; j < 4; j++) {
        int k = k0 + ty + j*8, n = n0 + tx;
        float v = (n < DIM6c) ? Dout[(size_t)k * DIM6c + n] * DSCALE : 0.f;
        t[ty + j*8][tx] = __half_as_ushort(__float2half_rn(v));
    }
    __syncthreads();
    #pragma unroll
    for (int j = 0; j < 4; j++) {
        int n = n0 + ty + j*8, k = k0 + tx;
        g_BnH[(size_t)n * Gc + k] = __ushort_as_half(t[tx][ty + j*8]);
    }
}

template<int L, int BBASE>
__device__ __forceinline__ void kWt_body(const float* __restrict__ wl, int lb, int tid) {
    constexpr int d = 2*L + 1;
    constexpr int Ndim = 64 * d;
    int idx = lb * 256 + tid;
    if (idx >= 16 * d * Ndim) return;
    int k = idx / Ndim, n = idx - k * Ndim;
    int f = k / d, u = k - f * d;
    int g2 = n / d, v = n - g2 * d;
    g_B[BBASE + idx] = f2tf32(wl[((f*64 + g2) * d + u) * d + v]);
}

__device__ __forceinline__ void kXC_body(const float* __restrict__ x, int b, int tid) {
    int idx2 = b * 256 + tid;                 // over XROWS*240 half2
    int r = idx2 / 240, j2 = idx2 - r * 240;
    int j = j2 * 2;
    float v0 = (j     < DIM6c) ? x[(size_t)r * DIM6c + j    ] : 0.f;
    float v1 = (j + 1 < DIM6c) ? x[(size_t)r * DIM6c + j + 1] : 0.f;
    *(__half2*)(g_xH + (size_t)r * PAD6 + j) = __floats2half2_rn(v0, v1);
}

__device__ __forceinline__ void kAux_body(const float* __restrict__ ico, int I,
                                          int b, int tid) {
    int idx = b * 256 + tid;
    if (idx < 64 * PAD6) {
        int n = idx / PAD6, j = idx - n * PAD6;
        g_icoH[idx] = (n < I && j < DIM6c) ?
            __float2half_rn(ico[(size_t)n * DIM6c + j]) : __float2half_rn(0.f);
    } else {
        int k = idx - 64 * PAD6;
        if (k < TROWS * 25) {
            int r = k / 25, j = DIM6c + (k - r * 25);
            g_TJh[(size_t)r * PAD6 + j] = __float2half_rn(0.f);
        }
    }
}

// block ranges
#define NB_H   32
#define NB_CVT 2048
#define NB_WT  1820
#define NB_XC  15360
#define NB_AUX 3320
#define O_CVT  (NB_H)
#define O_WT   (O_CVT + NB_CVT)
#define O_XC   (O_WT + NB_WT)
#define O_AUX  (O_XC + NB_XC)
#define NB_ALL (O_AUX + NB_AUX)

__global__ __launch_bounds__(256) void kPrep(
    const float* traj, const float* w1s, const float* w1v,
    const float* Dout, const float* x, const float* ico, int I,
    const float* w0, const float* w1, const float* w2p, const float* w3,
    const float* w4, const float* w5, const float* w6) {
    __shared__ unsigned short t[32][33];
    const int b = blockIdx.x, tid = threadIdx.x;
    if (b < NB_H) {
        kH_body(traj, w1s, w1v, b, tid);
    } else if (b < O_WT) {
        kCvtT_body(Dout, t, b - O_CVT, tid);
    } else if (b < O_XC) {
        int lb = b - O_WT;
        // cumulative 4d^2 blocks: 4,40,140,336,660,1144,1820
        if      (lb < 4)    kWt_body<0,BB0>(w0,  lb,        tid);
        else if (lb < 40)   kWt_body<1,BB1>(w1,  lb - 4,    tid);
        else if (lb < 140)  kWt_body<2,BB2>(w2p, lb - 40,   tid);
        else if (lb < 336)  kWt_body<3,BB3>(w3,  lb - 140,  tid);
        else if (lb < 660)  kWt_body<4,BB4>(w4,  lb - 336,  tid);
        else if (lb < 1144) kWt_body<5,BB5>(w5,  lb - 660,  tid);
        else                kWt_body<6,BB6>(w6,  lb - 1144, tid);
    } else if (b < O_AUX) {
        kXC_body(x, b - O_XC, tid);
    } else {
        kAux_body(ico, I, b - O_AUX, tid);
    }
}

// ============ kSig: g_sigH[m][k] = fp16(relu(H[m].Din[k])), half2 stores ====
__global__ __launch_bounds__(256) void kSig(const float* __restrict__ Din) {
    __shared__ float Hs[32][10];
    const int m0 = blockIdx.y * 32;
    const int k0 = blockIdx.x * 512 + threadIdx.x * 2;
    for (int i = threadIdx.x; i < 320; i += 256)
        Hs[i/10][i%10] = g_H[m0*10 + i];
    __syncthreads();
    float dr0[10], dr1[10];
    #pragma unroll
    for (int q = 0; q < 10; q++) { dr0[q] = Din[k0*10 + q]; dr1[q] = Din[k0*10 + 10 + q]; }
    #pragma unroll 4
    for (int m = 0; m < 32; m++) {
        float a0 = 0.f, a1 = 0.f;
        #pragma unroll
        for (int q = 0; q < 10; q++) { a0 += Hs[m][q] * dr0[q]; a1 += Hs[m][q] * dr1[q]; }
        __half2 h = __floats2half2_rn(fmaxf(a0, 0.f), fmaxf(a1, 0.f));
        *(__half2*)(g_sigH + (size_t)(m0 + m) * Gc + k0) = h;
    }
}

// ===== scatter one C element straight into per-l tf32 A =====
__device__ __forceinline__ void scatterA(int row, int col, float val) {
    if (col >= DIM6c) return;
    unsigned int tv = f2tf32(val);
    int bt = row >> 4, f = row & 15;
    if (col < 1) {
        g_A[AB0 + f * 512 + bt] = tv;
    } else if (col < 10) {
        int r = col - 1, u = r / 3, m = r - u*3;
        g_A[AB1 + (f*3 + u) * (512*3) + bt*3 + m] = tv;
    } else if (col < 35) {
        int r = col - 10, u = r / 5, m = r - u*5;
        g_A[AB2 + (f*5 + u) * (512*5) + bt*5 + m] = tv;
    } else if (col < 84) {
        int r = col - 35, u = r / 7, m = r - u*7;
        g_A[AB3 + (f*7 + u) * (512*7) + bt*7 + m] = tv;
    } else if (col < 165) {
        int r = col - 84, u = r / 9, m = r - u*9;
        g_A[AB4 + (f*9 + u) * (512*9) + bt*9 + m] = tv;
    } else if (col < 286) {
        int r = col - 165, u = r / 11, m = r - u*11;
        g_A[AB5 + (f*11 + u) * (512*11) + bt*11 + m] = tv;
    } else {
        int r = col - 286, u = r / 13, m = r - u*13;
        g_A[AB6 + (f*13 + u) * (512*13) + bt*13 + m] = tv;
    }
}

// ============ kBh: fp16 mma GEMM with ldmatrix. CTA 128x128, BK=64 ====
#define STAGE_B 18432              // 128*72*2 bytes
__global__ __launch_bounds__(256) void kBh() {
    extern __shared__ __align__(16) char smb[];
    const int n0 = blockIdx.x * 128;
    const int m0 = blockIdx.y * 128;
    const int tid = threadIdx.x;
    const int wid = tid >> 5, lane = tid & 31;
    const int wm = wid >> 1, wn = wid & 1;
    const int lr = lane >> 2;
    const int lc = lane & 3;

    float acc[2][8][4];
    #pragma unroll
    for (int mi = 0; mi < 2; mi++)
        #pragma unroll
        for (int nj = 0; nj < 8; nj++)
            #pragma unroll
            for (int r = 0; r < 4; r++) acc[mi][nj][r] = 0.f;

    auto issue = [&](int buf, int k0) {
        #pragma unroll
        for (int i = 0; i < 4; i++) {
            int id = tid + i*256;
            int row = id >> 3, cc = id & 7;
            CP_ASYNC16(smem_u32(smb + buf*STAGE_B + row*144 + cc*16),
                       g_sigH + (size_t)(m0 + row) * Gc + k0 + cc*8);
            CP_ASYNC16(smem_u32(smb + 2*STAGE_B + buf*STAGE_B + row*144 + cc*16),
                       g_BnH + (size_t)(n0 + row) * Gc + k0 + cc*8);
        }
    };

    issue(0, 0);  CP_COMMIT();
    issue(1, 64); CP_COMMIT();

    const int a_row_in = (lane & 15);
    const int a_koff   = (lane >> 4) << 4;
    const int b_row_in = ((lane >> 4) << 3) + (lane & 7);
    const int b_koff   = ((lane >> 3) & 1) << 4;

    const int NIT = Gc / 64;
    for (int it = 0; it < NIT; it++) {
        const int buf = it & 1;
        const unsigned int Abase = smem_u32(smb + buf*STAGE_B);
        const unsigned int Bbase = smem_u32(smb + 2*STAGE_B + buf*STAGE_B);
        CP_WAIT1();
        __syncthreads();

        #pragma unroll
        for (int kc = 0; kc < 4; kc++) {
            unsigned int afr[2][4];
            #pragma unroll
            for (int mi = 0; mi < 2; mi++) {
                int row = wm*32 + mi*16 + a_row_in;
                LDSM4(afr[mi][0], afr[mi][1], afr[mi][2], afr[mi][3],
                      Abase + row*144 + kc*32 + a_koff);
            }
            unsigned int bfr[8][2];
            #pragma unroll
            for (int njp = 0; njp < 4; njp++) {
                int row = wn*64 + njp*16 + b_row_in;
                LDSM4(bfr[2*njp][0], bfr[2*njp][1], bfr[2*njp+1][0], bfr[2*njp+1][1],
                      Bbase + row*144 + kc*32 + b_koff);
            }
            #pragma unroll
            for (int nj = 0; nj < 8; nj++)
                #pragma unroll
                for (int mi = 0; mi < 2; mi++)
                    MMA_F16(acc[mi][nj][0], acc[mi][nj][1], acc[mi][nj][2], acc[mi][nj][3],
                            afr[mi][0], afr[mi][1], afr[mi][2], afr[mi][3],
                            bfr[nj][0], bfr[nj][1]);
        }
        __syncthreads();
        int nk = (it + 2) * 64;
        if (nk < Gc) issue(buf, nk);
        CP_COMMIT();
    }

    #pragma unroll
    for (int mi = 0; mi < 2; mi++) {
        #pragma unroll
        for (int nj = 0; nj < 8; nj++) {
            int row = m0 + wm*32 + mi*16 + lr;
            int col = n0 + wn*64 + nj*8 + lc*2;
            scatterA(row,     col,     acc[mi][nj][0] * DUNSCALE);
            scatterA(row,     col + 1, acc[mi][nj][1] * DUNSCALE);
            scatterA(row + 8, col,     acc[mi][nj][2] * DUNSCALE);
            scatterA(row + 8, col + 1, acc[mi][nj][3] * DUNSCALE);
        }
    }
}

// ============ kCgemm: per-l C = A_l @ B_l (tf32), 2-stage cp.async =========
template<int L, int OFF, int ABASE, int BBASE>
__device__ __forceinline__ void kCmma_body(unsigned int (*As)[16][136],
                                           unsigned int (*Bs)[16][72]) {
    constexpr int d    = 2*L + 1;
    constexpr int Mdim = 512 * d;
    constexpr int Ndim = 64 * d;
    constexpr int K    = 16 * d;
    constexpr int TM   = Mdim / 128;
    constexpr int TN   = Ndim / 64;
    const int tile = blockIdx.x;
    if (tile >= TM * TN) return;
    const int m0 = (tile % TM) * 128;
    const int n0 = (tile / TM) * 64;
    const int tid = threadIdx.x;
    const int wid = tid >> 5, lane = tid & 31;
    const int wm = wid >> 1, wn = wid & 1;
    const int lr = lane >> 2, lc = lane & 3;

    float acc[2][4][4];
    #pragma unroll
    for (int mi = 0; mi < 2; mi++)
        #pragma unroll
        for (int nj = 0; nj < 4; nj++)
            #pragma unroll
            for (int r = 0; r < 4; r++) acc[mi][nj][r] = 0.f;

    auto issue = [&](int buf, int k0) {
        #pragma unroll
        for (int i = 0; i < 2; i++) {
            int idx = tid + i*256;
            int k = idx >> 5, c4 = (idx & 31) * 4;
            CP_ASYNC16(smem_u32(&As[buf][k][c4]),
                       g_A + ABASE + (size_t)(k0 + k) * Mdim + m0 + c4);
        }
        {
            int k = tid >> 4, c4 = (tid & 15) * 4;
            CP_ASYNC16(smem_u32(&Bs[buf][k][c4]),
                       g_B + BBASE + (size_t)(k0 + k) * Ndim + n0 + c4);
        }
    };

    constexpr int NK = K / 16;
    issue(0, 0); CP_COMMIT();
    if (NK > 1) issue(1, 16);
    CP_COMMIT();

    for (int it = 0; it < NK; it++) {
        const int buf = it & 1;
        CP_WAIT1();
        __syncthreads();

        #pragma unroll
        for (int kc = 0; kc < 2; kc++) {
            const int kb = kc * 8;
            unsigned int afr[2][4];
            #pragma unroll
            for (int mi = 0; mi < 2; mi++) {
                int rb = wm*32 + mi*16 + lr;
                afr[mi][0] = As[buf][kb + lc    ][rb    ];
                afr[mi][1] = As[buf][kb + lc    ][rb + 8];
                afr[mi][2] = As[buf][kb + lc + 4][rb    ];
                afr[mi][3] = As[buf][kb + lc + 4][rb + 8];
            }
            #pragma unroll
            for (int nj = 0; nj < 4; nj++) {
                int nb = wn*32 + nj*8 + lr;
                unsigned int b0 = Bs[buf][kb + lc    ][nb];
                unsigned int b1 = Bs[buf][kb + lc + 4][nb];
                #pragma unroll
                for (int mi = 0; mi < 2; mi++)
                    MMA_TF32(acc[mi][nj][0], acc[mi][nj][1], acc[mi][nj][2], acc[mi][nj][3],
                             afr[mi][0], afr[mi][1], afr[mi][2], afr[mi][3], b0, b1);
            }
        }
        __syncthreads();
        int nk = (it + 2) * 16;
        if (nk < K) issue(buf, nk);
        CP_COMMIT();
    }

    const float scale = 0.25f * rsqrtf((float)d);
    #pragma unroll
    for (int mi = 0; mi < 2; mi++) {
        #pragma unroll
        for (int nj = 0; nj < 4; nj++) {
            #pragma unroll
            for (int rr = 0; rr < 2; rr++) {
                int row = m0 + wm*32 + mi*16 + lr + rr*8;
                int bt = row / d, mm = row - bt * d;
                #pragma unroll
                for (int cc = 0; cc < 2; cc++) {
                    int col = n0 + wn*32 + nj*8 + lc*2 + cc;
                    int g2 = col / d, v = col - g2 * d;
                    g_TJh[(size_t)(bt*64 + g2) * PAD6 + OFF + v*d + mm] =
                        __float2half_rn(acc[mi][nj][rr*2 + cc] * scale);
                }
            }
        }
    }
}
__global__ __launch_bounds__(256) void kCgemm() {
    __shared__ unsigned int As[2][16][136];
    __shared__ unsigned int Bs[2][16][72];
    switch (blockIdx.y) {
        case 0: kCmma_body<0,0,  AB0,BB0>(As,Bs); break;
        case 1: kCmma_body<1,1,  AB1,BB1>(As,Bs); break;
        case 2: kCmma_body<2,10, AB2,BB2>(As,Bs); break;
        case 3: kCmma_body<3,35, AB3,BB3>(As,Bs); break;
        case 4: kCmma_body<4,84, AB4,BB4>(As,Bs); break;
        case 5: kCmma_body<5,165,AB5,BB5>(As,Bs); break;
        case 6: kCmma_body<6,286,AB6,BB6>(As,Bs); break;
    }
}

// ============ kDmma: fp16 mma, cp.async fills from fp16 padded sources ======
__global__ __launch_bounds__(256) void kDmma(float* __restrict__ out, int I) {
    __shared__ __align__(16) __half As[128][36];
    __shared__ __align__(16) __half Bs[64][36];
    const int r0 = blockIdx.x * 128;
    const __half* Ap = (r0 < XROWS) ? (g_xH + (size_t)r0 * PAD6)
                                    : (g_TJh + (size_t)(r0 - XROWS) * PAD6);
    const int tid = threadIdx.x;
    const int wid = tid >> 5, lane = tid & 31;
    const int wm = wid >> 1, wn = wid & 1;
    const int lr = lane >> 2;
    const int lc = lane & 3;
    const unsigned int* A32 = (const unsigned int*)&As[0][0];
    const unsigned int* B32 = (const unsigned int*)&Bs[0][0];

    float acc[2][4][4];
    #pragma unroll
    for (int mi = 0; mi < 2; mi++)
        #pragma unroll
        for (int nj = 0; nj < 4; nj++)
            #pragma unroll
            for (int r = 0; r < 4; r++) acc[mi][nj][r] = 0.f;

    for (int j0 = 0; j0 < PAD6; j0 += 32) {
        #pragma unroll
        for (int i = 0; i < 4; i++) {
            int id = tid + i*256;
            int r = id >> 3, ch = id & 7;
            CP_ASYNC8(smem_u32((char*)&As[0][0] + r*72 + ch*8),
                      Ap + (size_t)r * PAD6 + j0 + ch*4);
        }
        #pragma unroll
        for (int i = 0; i < 2; i++) {
            int id = tid + i*256;
            int n = id >> 3, ch = id & 7;
            CP_ASYNC8(smem_u32((char*)&Bs[0][0] + n*72 + ch*8),
                      g_icoH + (size_t)n * PAD6 + j0 + ch*4);
        }
        CP_COMMIT();
        CP_WAIT0();
        __syncthreads();

        #pragma unroll
        for (int kc = 0; kc < 2; kc++) {
            const int w0 = kc*8 + lc;
            unsigned int afr[2][4];
            #pragma unroll
            for (int mi = 0; mi < 2; mi++) {
                int rb = wm*32 + mi*16 + lr;
                afr[mi][0] = A32[(rb    )*18 + w0    ];
                afr[mi][1] = A32[(rb + 8)*18 + w0    ];
                afr[mi][2] = A32[(rb    )*18 + w0 + 4];
                afr[mi][3] = A32[(rb + 8)*18 + w0 + 4];
            }
            #pragma unroll
            for (int nj = 0; nj < 4; nj++) {
                int nb = wn*32 + nj*8 + lr;
                unsigned int b0 = B32[nb*18 + w0    ];
                unsigned int b1 = B32[nb*18 + w0 + 4];
                #pragma unroll
                for (int mi = 0; mi < 2; mi++)
                    MMA_F16(acc[mi][nj][0], acc[mi][nj][1], acc[mi][nj][2], acc[mi][nj][3],
                            afr[mi][0], afr[mi][1], afr[mi][2], afr[mi][3], b0, b1);
            }
        }
        __syncthreads();
    }

    #pragma unroll
    for (int mi = 0; mi < 2; mi++) {
        #pragma unroll
        for (int nj = 0; nj < 4; nj++) {
            int row = r0 + wm*32 + mi*16 + lr;
            int col = wn*32 + nj*8 + lc*2;
            if (col < I) {
                out[(size_t)row * I + col] = acc[mi][nj][0];
                out[(size_t)(row + 8) * I + col] = acc[mi][nj][2];
                if (col + 1 < I) {
                    out[(size_t)row * I + col + 1] = acc[mi][nj][1];
                    out[(size_t)(row + 8) * I + col + 1] = acc[mi][nj][3];
                }
            }
        }
    }
}

extern "C" void kernel_launch(void* const* d_in, const int* in_sizes, int n_in,
                              void* d_out, int out_size) {
    const float *x = nullptr, *traj = nullptr, *w1s = nullptr, *w1v = nullptr;
    const float *Din = nullptr, *Dout = nullptr, *ico = nullptr;
    const float* w2[7] = {};
    int icoN = 60;

    for (int i = 0; i < n_in; i++) {
        int sz = in_sizes[i];
        const float* p = (const float*)d_in[i];
        switch (sz) {
            case 7454720: x    = p; break;
            case 5120:    traj = p; break;
            case 16:      w1s  = p; break;
            case 144:     w1v  = p; break;
            case 40960:   Din  = p; break;
            case 1863680: Dout = p; break;
            case 1024:    w2[0] = p; break;
            case 9216:    w2[1] = p; break;
            case 25600:   w2[2] = p; break;
            case 50176:   w2[3] = p; break;
            case 82944:   w2[4] = p; break;
            case 123904:  w2[5] = p; break;
            case 173056:  w2[6] = p; break;
            default:      ico = p; icoN = sz / DIM6c; break;
        }
    }
    float* out = (float*)d_out;

    const int SMEMB = 4 * STAGE_B;   // 73728 bytes
    cudaFuncSetAttribute(kBh, cudaFuncAttributeMaxDynamicSharedMemorySize, SMEMB);

    kPrep<<<NB_ALL, 256>>>(traj, w1s, w1v, Dout, x, ico, icoN,
                           w2[0], w2[1], w2[2], w2[3], w2[4], w2[5], w2[6]);
    kSig<<<dim3(Gc/512, MROWS/32), 256>>>(Din);

    kBh<<<dim3(4, MROWS/128), 256, SMEMB>>>();

    kCgemm<<<dim3(676, 7), 256>>>();

    kDmma<<<(XROWS + TROWS)/128, 256>>>(out, icoN);
}